// round 2
// baseline (speedup 1.0000x reference)
#include <cuda_runtime.h>

#define NB   64
#define LL   128
#define DIN  128
#define DH   128
#define PAD  132
#define NEGV -100000000.0f

// scratch for h2 = relu(relu(x@W1+b1)@W2+b2), (N, L, DH)
__device__ float g_h2[NB * LL * DH];

// Load a contiguous 128x128 row-major tile, storing TRANSPOSED into smem [k][l] with PAD.
__device__ __forceinline__ void load_tile_transposed(float* As, const float* __restrict__ src, int tid) {
    #pragma unroll
    for (int i = tid; i < 4096; i += 256) {
        int l = i >> 5;            // row in source
        int k = (i & 31) << 2;     // starting col in source
        float4 v = reinterpret_cast<const float4*>(src)[i];
        As[(k + 0) * PAD + l] = v.x;
        As[(k + 1) * PAD + l] = v.y;
        As[(k + 2) * PAD + l] = v.z;
        As[(k + 3) * PAD + l] = v.w;
    }
}

// Load a 128x128 tile (row stride = stride floats) row-major into smem [r][c] with PAD.
__device__ __forceinline__ void load_tile(float* Bs, const float* __restrict__ src, int stride, int tid) {
    #pragma unroll
    for (int i = tid; i < 4096; i += 256) {
        int r  = i >> 5;
        int c4 = i & 31;
        float4 v = reinterpret_cast<const float4*>(src + (size_t)r * stride)[c4];
        *reinterpret_cast<float4*>(&Bs[r * PAD + (c4 << 2)]) = v;
    }
}

// C[128,128] += A[128,128] @ B[128,128]; As is k-major (transposed A), Bs row-major, both PAD.
// Thread (tr, tc) owns rows tr*8..+7, cols tc*8..+7.  tid = tc*16 + tr  (B reads broadcast).
__device__ __forceinline__ void gemm128(const float* As, const float* Bs, float acc[8][8], int tr, int tc) {
    #pragma unroll 4
    for (int k = 0; k < 128; ++k) {
        float4 a0 = *reinterpret_cast<const float4*>(&As[k * PAD + tr * 8]);
        float4 a1 = *reinterpret_cast<const float4*>(&As[k * PAD + tr * 8 + 4]);
        float4 b0 = *reinterpret_cast<const float4*>(&Bs[k * PAD + tc * 8]);
        float4 b1 = *reinterpret_cast<const float4*>(&Bs[k * PAD + tc * 8 + 4]);
        float a[8] = {a0.x, a0.y, a0.z, a0.w, a1.x, a1.y, a1.z, a1.w};
        float b[8] = {b0.x, b0.y, b0.z, b0.w, b1.x, b1.y, b1.z, b1.w};
        #pragma unroll
        for (int i = 0; i < 8; ++i)
            #pragma unroll
            for (int j = 0; j < 8; ++j)
                acc[i][j] = fmaf(a[i], b[j], acc[i][j]);
    }
}

// ---------------------------------------------------------------------------
// Kernel 1: per-n fused 2-layer MLP -> g_h2
// ---------------------------------------------------------------------------
__global__ void __launch_bounds__(256, 1) k1_mlp(
    const float* __restrict__ x,  const float* __restrict__ W1, const float* __restrict__ b1,
    const float* __restrict__ W2, const float* __restrict__ b2)
{
    extern __shared__ float sm[];
    float* As = sm;                // [128][PAD]
    float* Bs = sm + 128 * PAD;    // [128][PAD]

    int n   = blockIdx.x;
    int tid = threadIdx.x;
    int tr  = tid & 15, tc = tid >> 4;

    load_tile_transposed(As, x + (size_t)n * LL * DIN, tid);   // As[k][l] = x[l][k]
    load_tile(Bs, W1, DH, tid);                                // Bs[k][j] = W1[k][j]
    __syncthreads();

    float acc[8][8];
    #pragma unroll
    for (int i = 0; i < 8; ++i)
        #pragma unroll
        for (int j = 0; j < 8; ++j) acc[i][j] = 0.0f;

    gemm128(As, Bs, acc, tr, tc);

    float bb[8];
    #pragma unroll
    for (int j = 0; j < 8; ++j) bb[j] = b1[tc * 8 + j];

    __syncthreads();   // GEMM1 reads of As/Bs complete

    // h1 = relu(acc + b1), write TRANSPOSED into As (As[c][l] = h1[l][c]); load W2 into Bs.
    #pragma unroll
    for (int i = 0; i < 8; ++i)
        #pragma unroll
        for (int j = 0; j < 8; ++j) {
            float v = fmaxf(acc[i][j] + bb[j], 0.0f);
            As[(tc * 8 + j) * PAD + (tr * 8 + i)] = v;
        }
    load_tile(Bs, W2, DH, tid);
    __syncthreads();

    #pragma unroll
    for (int i = 0; i < 8; ++i)
        #pragma unroll
        for (int j = 0; j < 8; ++j) acc[i][j] = 0.0f;

    gemm128(As, Bs, acc, tr, tc);

    #pragma unroll
    for (int j = 0; j < 8; ++j) bb[j] = b2[tc * 8 + j];

    float* dst = g_h2 + (size_t)n * LL * DH;
    #pragma unroll
    for (int i = 0; i < 8; ++i) {
        int l = tr * 8 + i;
        float4 o0, o1;
        o0.x = fmaxf(acc[i][0] + bb[0], 0.0f);
        o0.y = fmaxf(acc[i][1] + bb[1], 0.0f);
        o0.z = fmaxf(acc[i][2] + bb[2], 0.0f);
        o0.w = fmaxf(acc[i][3] + bb[3], 0.0f);
        o1.x = fmaxf(acc[i][4] + bb[4], 0.0f);
        o1.y = fmaxf(acc[i][5] + bb[5], 0.0f);
        o1.z = fmaxf(acc[i][6] + bb[6], 0.0f);
        o1.w = fmaxf(acc[i][7] + bb[7], 0.0f);
        *reinterpret_cast<float4*>(&dst[l * DH + tc * 8])     = o0;
        *reinterpret_cast<float4*>(&dst[l * DH + tc * 8 + 4]) = o1;
    }
}

// ---------------------------------------------------------------------------
// Kernel 2: per-(n,h) fused  filt-tile GEMM + masked column softmax + x-contraction
// ---------------------------------------------------------------------------
__global__ void __launch_bounds__(256, 1) k2_filter(
    const float* __restrict__ x,    const float* __restrict__ mask,
    const float* __restrict__ W3,   const float* __restrict__ b3,
    const float* __restrict__ tbias, float* __restrict__ out)
{
    extern __shared__ float sm[];
    float* As  = sm;                   // h2^T for GEMM, then filt tile [l][f]
    float* Bs  = sm + 128 * PAD;       // W3 slice, then x tile [l][f]
    float* msk = sm + 2 * 128 * PAD;   // 128 floats
    float* red = msk + 128;            // 4 floats

    int h   = blockIdx.x;
    int n   = blockIdx.y;
    int tid = threadIdx.x;
    int tr  = tid & 15, tc = tid >> 4;

    load_tile_transposed(As, g_h2 + (size_t)n * LL * DH, tid);           // As[k][l] = h2[l][k]
    load_tile(Bs, W3 + (size_t)h * DIN, DIN * DH /*16384*/, tid);        // Bs[k][f] = W3[k][h*128+f]
    if (tid < LL) msk[tid] = mask[n * LL + tid];
    __syncthreads();

    float acc[8][8];
    #pragma unroll
    for (int i = 0; i < 8; ++i)
        #pragma unroll
        for (int j = 0; j < 8; ++j) acc[i][j] = 0.0f;

    gemm128(As, Bs, acc, tr, tc);

    float bb[8];
    #pragma unroll
    for (int j = 0; j < 8; ++j) bb[j] = b3[(size_t)h * DIN + tc * 8 + j];

    __syncthreads();   // done reading As/Bs

    // filt tile into As row-major [l][f]; x tile into Bs
    #pragma unroll
    for (int i = 0; i < 8; ++i)
        #pragma unroll
        for (int j = 0; j < 8; ++j)
            As[(tr * 8 + i) * PAD + (tc * 8 + j)] = acc[i][j] + bb[j];
    load_tile(Bs, x + (size_t)n * LL * DIN, DIN, tid);
    __syncthreads();

    // One thread per feature column f: masked softmax over l, dot with x column.
    if (tid < 128) {
        int f = tid;
        float m = -3.4e38f;
        #pragma unroll 8
        for (int l = 0; l < 128; ++l) {
            float mk = msk[l];
            float v  = As[l * PAD + f] * mk + (1.0f - mk) * NEGV;
            m = fmaxf(m, v);
        }
        float s = 0.0f, p = 0.0f;
        #pragma unroll 8
        for (int l = 0; l < 128; ++l) {
            float mk = msk[l];
            float v  = As[l * PAD + f] * mk + (1.0f - mk) * NEGV;
            float e  = __expf(v - m);
            s += e;
            p = fmaf(Bs[l * PAD + f], e, p);
        }
        float r = p / s;
        #pragma unroll
        for (int off = 16; off; off >>= 1)
            r += __shfl_xor_sync(0xffffffffu, r, off);
        if ((tid & 31) == 0) red[tid >> 5] = r;
    }
    __syncthreads();

    if (tid == 0) {
        float s = red[0] + red[1] + red[2] + red[3];
        out[n * DH + h] = fmaxf(s + tbias[h], 0.0f);
    }
}

// ---------------------------------------------------------------------------
extern "C" void kernel_launch(void* const* d_in, const int* in_sizes, int n_in,
                              void* d_out, int out_size) {
    const float* x    = (const float*)d_in[0];
    const float* mask = (const float*)d_in[1];
    const float* W1   = (const float*)d_in[2];
    const float* b1   = (const float*)d_in[3];
    const float* W2   = (const float*)d_in[4];
    const float* b2   = (const float*)d_in[5];
    const float* W3   = (const float*)d_in[6];
    const float* b3   = (const float*)d_in[7];
    const float* tb   = (const float*)d_in[8];
    float* out = (float*)d_out;

    const int smem1 = 2 * 128 * PAD * (int)sizeof(float);
    const int smem2 = (2 * 128 * PAD + 128 + 4) * (int)sizeof(float);

    cudaFuncSetAttribute(k1_mlp,    cudaFuncAttributeMaxDynamicSharedMemorySize, smem1);
    cudaFuncSetAttribute(k2_filter, cudaFuncAttributeMaxDynamicSharedMemorySize, smem2);

    k1_mlp<<<NB, 256, smem1>>>(x, W1, b1, W2, b2);
    k2_filter<<<dim3(DH, NB), 256, smem2>>>(x, mask, W3, b3, tb, out);
}

// round 6
// speedup vs baseline: 2.2333x; 2.2333x over previous
#include <cuda_runtime.h>
#include <cuda_bf16.h>
#include <cstdint>

#define NB   64
#define LL   128
#define DIN  128
#define DH   128
#define PAD  132     // fp32 smem pitch for k1
#define PITCH 136    // bf16 smem pitch for k2 mma tiles (272B rows: 16B-aligned, conflict-free)
#define FPITCH 130   // fp32 smem pitch for filt dump

extern __shared__ char dynsm[];

// ---------------------------------------------------------------------------
// Global scratch (allocation-free)
// ---------------------------------------------------------------------------
__device__ __nv_bfloat16 g_W3t_hi[DH * DIN * DH];   // [h][f][k] = W3[k][h*128+f]
__device__ __nv_bfloat16 g_W3t_lo[DH * DIN * DH];
__device__ __nv_bfloat16 g_h2hi[NB * LL * DH];      // [n][l][k]
__device__ __nv_bfloat16 g_h2lo[NB * LL * DH];

// ---------------------------------------------------------------------------
// fast exp (FFMA pipe, no MUFU). Valid for |v| small-ish; upper-clamped.
// ---------------------------------------------------------------------------
__device__ __forceinline__ float fexp(float a) {
    float t = fminf(fmaxf(a * 1.4426950408889634f, -126.0f), 126.0f);
    float k = rintf(t);
    float r = t - k;
    float p = 1.3333558e-3f;
    p = fmaf(p, r, 9.6181291e-3f);
    p = fmaf(p, r, 5.5504109e-2f);
    p = fmaf(p, r, 2.4022651e-1f);
    p = fmaf(p, r, 6.9314718e-1f);
    p = fmaf(p, r, 1.0f);
    return __int_as_float(((int)k + 127) << 23) * p;
}

// mma.sync m16n8k16 bf16 (sm_80+; works on sm_100 base target)
__device__ __forceinline__ void mma16816(float* c, const uint32_t* a, const uint32_t* b) {
    asm volatile(
        "mma.sync.aligned.m16n8k16.row.col.f32.bf16.bf16.f32 "
        "{%0,%1,%2,%3}, {%4,%5,%6,%7}, {%8,%9}, {%0,%1,%2,%3};"
        : "+f"(c[0]), "+f"(c[1]), "+f"(c[2]), "+f"(c[3])
        : "r"(a[0]), "r"(a[1]), "r"(a[2]), "r"(a[3]), "r"(b[0]), "r"(b[1]));
}

// Copy a row-major [128][128] bf16 tile (global) into smem with row pitch PITCH.
__device__ __forceinline__ void cp_tile(__nv_bfloat16* dst, const __nv_bfloat16* src, int tid) {
    const uint4* s = reinterpret_cast<const uint4*>(src);
    #pragma unroll
    for (int i = tid; i < 2048; i += 256) {
        int r = i >> 4, c = (i & 15) << 3;
        *reinterpret_cast<uint4*>(dst + r * PITCH + c) = s[i];
    }
}

// ---------------------------------------------------------------------------
// k0: transpose + bf16-split W3: g_W3t[h][f][k] = W3[k][h*128+f]
// ---------------------------------------------------------------------------
__global__ void __launch_bounds__(256) k0_w3t(const float* __restrict__ W3) {
    float* s = reinterpret_cast<float*>(dynsm);     // [128][129]
    int h = blockIdx.x, tid = threadIdx.x;
    for (int i = tid; i < 16384; i += 256) {
        int k = i >> 7, f = i & 127;
        s[k * 129 + f] = W3[(size_t)k * (DIN * DH) + h * DIN + f];
    }
    __syncthreads();
    for (int i = tid; i < 16384; i += 256) {
        int f = i >> 7, k = i & 127;
        float v = s[k * 129 + f];
        __nv_bfloat16 hi = __float2bfloat16(v);
        __nv_bfloat16 lo = __float2bfloat16(v - __bfloat162float(hi));
        size_t o = ((size_t)h * DIN + f) * DH + k;
        g_W3t_hi[o] = hi;
        g_W3t_lo[o] = lo;
    }
}

// ---------------------------------------------------------------------------
// k1: per-n fused 2-layer SIMT MLP -> g_h2 hi/lo bf16 planes
// ---------------------------------------------------------------------------
__device__ __forceinline__ void load_tile_transposed(float* As, const float* __restrict__ src, int tid) {
    #pragma unroll
    for (int i = tid; i < 4096; i += 256) {
        int l = i >> 5, k = (i & 31) << 2;
        float4 v = reinterpret_cast<const float4*>(src)[i];
        As[(k + 0) * PAD + l] = v.x;
        As[(k + 1) * PAD + l] = v.y;
        As[(k + 2) * PAD + l] = v.z;
        As[(k + 3) * PAD + l] = v.w;
    }
}
__device__ __forceinline__ void load_tile(float* Bs, const float* __restrict__ src, int stride, int tid) {
    #pragma unroll
    for (int i = tid; i < 4096; i += 256) {
        int r = i >> 5, c4 = i & 31;
        float4 v = reinterpret_cast<const float4*>(src + (size_t)r * stride)[c4];
        *reinterpret_cast<float4*>(&Bs[r * PAD + (c4 << 2)]) = v;
    }
}
__device__ __forceinline__ void gemm128(const float* As, const float* Bs, float acc[8][8], int tr, int tc) {
    #pragma unroll 4
    for (int k = 0; k < 128; ++k) {
        float4 a0 = *reinterpret_cast<const float4*>(&As[k * PAD + tr * 8]);
        float4 a1 = *reinterpret_cast<const float4*>(&As[k * PAD + tr * 8 + 4]);
        float4 b0 = *reinterpret_cast<const float4*>(&Bs[k * PAD + tc * 8]);
        float4 b1 = *reinterpret_cast<const float4*>(&Bs[k * PAD + tc * 8 + 4]);
        float a[8] = {a0.x, a0.y, a0.z, a0.w, a1.x, a1.y, a1.z, a1.w};
        float b[8] = {b0.x, b0.y, b0.z, b0.w, b1.x, b1.y, b1.z, b1.w};
        #pragma unroll
        for (int i = 0; i < 8; ++i)
            #pragma unroll
            for (int j = 0; j < 8; ++j)
                acc[i][j] = fmaf(a[i], b[j], acc[i][j]);
    }
}

__global__ void __launch_bounds__(256, 1) k1_mlp(
    const float* __restrict__ x,  const float* __restrict__ W1, const float* __restrict__ b1,
    const float* __restrict__ W2, const float* __restrict__ b2)
{
    float* As = reinterpret_cast<float*>(dynsm);
    float* Bs = As + 128 * PAD;
    int n = blockIdx.x, tid = threadIdx.x;
    int tr = tid & 15, tc = tid >> 4;

    load_tile_transposed(As, x + (size_t)n * LL * DIN, tid);
    load_tile(Bs, W1, DH, tid);
    __syncthreads();

    float acc[8][8];
    #pragma unroll
    for (int i = 0; i < 8; ++i)
        #pragma unroll
        for (int j = 0; j < 8; ++j) acc[i][j] = 0.0f;
    gemm128(As, Bs, acc, tr, tc);

    float bb[8];
    #pragma unroll
    for (int j = 0; j < 8; ++j) bb[j] = b1[tc * 8 + j];
    __syncthreads();

    #pragma unroll
    for (int i = 0; i < 8; ++i)
        #pragma unroll
        for (int j = 0; j < 8; ++j)
            As[(tc * 8 + j) * PAD + (tr * 8 + i)] = fmaxf(acc[i][j] + bb[j], 0.0f);
    load_tile(Bs, W2, DH, tid);
    __syncthreads();

    #pragma unroll
    for (int i = 0; i < 8; ++i)
        #pragma unroll
        for (int j = 0; j < 8; ++j) acc[i][j] = 0.0f;
    gemm128(As, Bs, acc, tr, tc);

    #pragma unroll
    for (int j = 0; j < 8; ++j) bb[j] = b2[tc * 8 + j];

    #pragma unroll
    for (int i = 0; i < 8; ++i) {
        int l = tr * 8 + i;
        size_t base = ((size_t)n * LL + l) * DH + tc * 8;
        #pragma unroll
        for (int j = 0; j < 8; ++j) {
            float v = fmaxf(acc[i][j] + bb[j], 0.0f);
            __nv_bfloat16 hi = __float2bfloat16(v);
            __nv_bfloat16 lo = __float2bfloat16(v - __bfloat162float(hi));
            g_h2hi[base + j] = hi;
            g_h2lo[base + j] = lo;
        }
    }
}

// ---------------------------------------------------------------------------
// k2: mma.sync split-bf16 filt tile + masked softmax + x contraction.
// grid = (2 hgroups, 64 n), 256 threads. h2/x/mask resident; W3t[h] streamed.
// ---------------------------------------------------------------------------
#define OFF_A    0                       // 2x(128*PITCH*2) = 69632; filt (66560) aliases here
#define OFF_B    69632                   // h2 hi/lo
#define OFF_X    139264                  // 65536 fp32
#define OFF_MASK 204800                  // 512
#define OFF_S    205312                  // 1024
#define OFF_D    206336                  // 1024
#define OFF_RED  207360                  // 16
#define K2_SMEM  207392

__global__ void __launch_bounds__(256, 1) k2_filter(
    const float* __restrict__ x, const float* __restrict__ mask,
    const float* __restrict__ tbias, float* __restrict__ out)
{
    char* sm = dynsm;
    __nv_bfloat16* sAhi = reinterpret_cast<__nv_bfloat16*>(sm + OFF_A);
    __nv_bfloat16* sAlo = sAhi + 128 * PITCH;
    float*         sF   = reinterpret_cast<float*>(sm + OFF_A);   // alias over A
    __nv_bfloat16* sBhi = reinterpret_cast<__nv_bfloat16*>(sm + OFF_B);
    __nv_bfloat16* sBlo = sBhi + 128 * PITCH;
    float* sX    = reinterpret_cast<float*>(sm + OFF_X);
    float* sMask = reinterpret_cast<float*>(sm + OFF_MASK);
    float* sS    = reinterpret_cast<float*>(sm + OFF_S);
    float* sD    = reinterpret_cast<float*>(sm + OFF_D);
    float* sRed  = reinterpret_cast<float*>(sm + OFF_RED);

    const int tid  = threadIdx.x;
    const int lane = tid & 31, wid = tid >> 5;
    const int g = lane >> 2, tq = lane & 3;
    const int mh = wid & 3;    // f0 = mh*32 (2 m-tiles of 16)
    const int nh = wid >> 2;   // l0 = nh*64 (8 n-tiles of 8)
    const int n  = blockIdx.y;
    const int hg = blockIdx.x;

    // resident: h2[n] hi/lo, x[n], mask[n]
    cp_tile(sBhi, g_h2hi + (size_t)n * LL * DH, tid);
    cp_tile(sBlo, g_h2lo + (size_t)n * LL * DH, tid);
    {
        const float4* xs = reinterpret_cast<const float4*>(x + (size_t)n * LL * DIN);
        float4* xd = reinterpret_cast<float4*>(sX);
        #pragma unroll
        for (int i = tid; i < 4096; i += 256) xd[i] = xs[i];
    }
    if (tid < 128) sMask[tid] = mask[n * LL + tid];

    const int ef = tid & 127, eh = tid >> 7;   // epilogue mapping

    for (int hi = 0; hi < 64; ++hi) {
        int h = hg * 64 + hi;
        __syncthreads();   // prev epilogue done reading sF (A region); first iter: covers resident loads

        cp_tile(sAhi, g_W3t_hi + (size_t)h * DIN * DH, tid);
        cp_tile(sAlo, g_W3t_lo + (size_t)h * DIN * DH, tid);
        __syncthreads();

        float acc[2][8][4];
        #pragma unroll
        for (int mt = 0; mt < 2; ++mt)
            #pragma unroll
            for (int nt = 0; nt < 8; ++nt)
                #pragma unroll
                for (int q = 0; q < 4; ++q) acc[mt][nt][q] = 0.0f;

        #pragma unroll 1
        for (int ks = 0; ks < 8; ++ks) {
            const int k0 = ks * 16;
            uint32_t ah[2][4], al[2][4];
            #pragma unroll
            for (int mt = 0; mt < 2; ++mt) {
                const __nv_bfloat16* r0h = sAhi + (mh * 32 + mt * 16 + g) * PITCH + k0 + 2 * tq;
                ah[mt][0] = *reinterpret_cast<const uint32_t*>(r0h);
                ah[mt][1] = *reinterpret_cast<const uint32_t*>(r0h + 8 * PITCH);
                ah[mt][2] = *reinterpret_cast<const uint32_t*>(r0h + 8);
                ah[mt][3] = *reinterpret_cast<const uint32_t*>(r0h + 8 * PITCH + 8);
                const __nv_bfloat16* r0l = sAlo + (mh * 32 + mt * 16 + g) * PITCH + k0 + 2 * tq;
                al[mt][0] = *reinterpret_cast<const uint32_t*>(r0l);
                al[mt][1] = *reinterpret_cast<const uint32_t*>(r0l + 8 * PITCH);
                al[mt][2] = *reinterpret_cast<const uint32_t*>(r0l + 8);
                al[mt][3] = *reinterpret_cast<const uint32_t*>(r0l + 8 * PITCH + 8);
            }
            #pragma unroll
            for (int nt = 0; nt < 8; ++nt) {
                const __nv_bfloat16* rbh = sBhi + (nh * 64 + nt * 8 + g) * PITCH + k0 + 2 * tq;
                uint32_t bh[2] = { *reinterpret_cast<const uint32_t*>(rbh),
                                   *reinterpret_cast<const uint32_t*>(rbh + 8) };
                const __nv_bfloat16* rbl = sBlo + (nh * 64 + nt * 8 + g) * PITCH + k0 + 2 * tq;
                uint32_t bl[2] = { *reinterpret_cast<const uint32_t*>(rbl),
                                   *reinterpret_cast<const uint32_t*>(rbl + 8) };
                #pragma unroll
                for (int mt = 0; mt < 2; ++mt) {
                    mma16816(acc[mt][nt], ah[mt], bh);
                    mma16816(acc[mt][nt], ah[mt], bl);
                    mma16816(acc[mt][nt], al[mt], bh);
                }
            }
        }
        __syncthreads();   // all warps done reading A — safe to alias filt over it

        // dump filt[f][l] (C frag: rows f0+g / f0+g+8, cols l0+2tq,+1 per n-tile)
        #pragma unroll
        for (int mt = 0; mt < 2; ++mt) {
            int f = mh * 32 + mt * 16 + g;
            #pragma unroll
            for (int nt = 0; nt < 8; ++nt) {
                int l = nh * 64 + nt * 8 + 2 * tq;
                *reinterpret_cast<float2*>(&sF[f * FPITCH + l]) =
                    make_float2(acc[mt][nt][0], acc[mt][nt][1]);
                *reinterpret_cast<float2*>(&sF[(f + 8) * FPITCH + l]) =
                    make_float2(acc[mt][nt][2], acc[mt][nt][3]);
            }
        }
        __syncthreads();

        // epilogue: thread (ef, eh) -> feature ef, l half eh. No max pass needed:
        // logits are O(1) (exp cannot overflow) and softmax is shift-invariant.
        float s = 0.0f, d = 0.0f;
        #pragma unroll 4
        for (int i = 0; i < 64; i += 2) {
            int l = eh * 64 + i;
            float2 v = *reinterpret_cast<const float2*>(&sF[ef * FPITCH + l]);
            float e0 = fexp(v.x) * sMask[l];
            float e1 = fexp(v.y) * sMask[l + 1];
            s += e0 + e1;
            d = fmaf(sX[l * DIN + ef], e0, d);
            d = fmaf(sX[(l + 1) * DIN + ef], e1, d);
        }
        sS[tid] = s;
        sD[tid] = d;
        __syncthreads();
        if (tid < 128) {
            float ss = sS[tid] + sS[tid + 128];
            float dd = sD[tid] + sD[tid + 128];
            float r = dd / ss;
            #pragma unroll
            for (int o = 16; o; o >>= 1) r += __shfl_xor_sync(0xffffffffu, r, o);
            if (lane == 0) sRed[wid] = r;
        }
        __syncthreads();
        if (tid == 0)
            out[n * DH + h] = fmaxf(sRed[0] + sRed[1] + sRed[2] + sRed[3] + tbias[h], 0.0f);
    }
}

// ---------------------------------------------------------------------------
extern "C" void kernel_launch(void* const* d_in, const int* in_sizes, int n_in,
                              void* d_out, int out_size) {
    const float* x    = (const float*)d_in[0];
    const float* mask = (const float*)d_in[1];
    const float* W1   = (const float*)d_in[2];
    const float* b1   = (const float*)d_in[3];
    const float* W2   = (const float*)d_in[4];
    const float* b2   = (const float*)d_in[5];
    const float* W3   = (const float*)d_in[6];
    // d_in[7] = b3: constant over l per feature -> cancels in the softmax
    const float* tb   = (const float*)d_in[8];
    float* out = (float*)d_out;

    const int smem0 = 128 * 129 * (int)sizeof(float);
    const int smem1 = 2 * 128 * PAD * (int)sizeof(float);
    const int smem2 = K2_SMEM;

    cudaFuncSetAttribute(k0_w3t,    cudaFuncAttributeMaxDynamicSharedMemorySize, smem0);
    cudaFuncSetAttribute(k1_mlp,    cudaFuncAttributeMaxDynamicSharedMemorySize, smem1);
    cudaFuncSetAttribute(k2_filter, cudaFuncAttributeMaxDynamicSharedMemorySize, smem2);

    k0_w3t<<<DH, 256, smem0>>>(W3);
    k1_mlp<<<NB, 256, smem1>>>(x, W1, b1, W2, b2);
    k2_filter<<<dim3(2, NB), 256, smem2>>>(x, mask, tb, out);
}

// round 7
// speedup vs baseline: 2.9017x; 1.2993x over previous
#include <cuda_runtime.h>
#include <cuda_bf16.h>
#include <cstdint>

#define NB   64
#define LL   128
#define DIN  128
#define DH   128
#define PAD  132        // fp32 pitch (k1)
#define PITCHB 272      // bf16 tile row pitch in BYTES (136 bf16)
#define APLANE 34816    // 128*272

extern __shared__ char dynsm[];

__device__ __nv_bfloat16 g_W3t_hi[DH * DIN * DH];   // [h][f][k]
__device__ __nv_bfloat16 g_W3t_lo[DH * DIN * DH];
__device__ __nv_bfloat16 g_h2hi[NB * LL * DH];      // [n][l][k]
__device__ __nv_bfloat16 g_h2lo[NB * LL * DH];

// ---------------------------------------------------------------------------
__device__ __forceinline__ uint32_t smem_u32(const void* p) {
    uint32_t a;
    asm("{ .reg .u64 t; cvta.to.shared.u64 t, %1; cvt.u32.u64 %0, t; }" : "=r"(a) : "l"(p));
    return a;
}
__device__ __forceinline__ float fexp(float a) {
    float t = fminf(fmaxf(a * 1.4426950408889634f, -126.0f), 126.0f);
    float k = rintf(t);
    float r = t - k;
    float p = 1.3333558e-3f;
    p = fmaf(p, r, 9.6181291e-3f);
    p = fmaf(p, r, 5.5504109e-2f);
    p = fmaf(p, r, 2.4022651e-1f);
    p = fmaf(p, r, 6.9314718e-1f);
    p = fmaf(p, r, 1.0f);
    return __int_as_float(((int)k + 127) << 23) * p;
}
__device__ __forceinline__ void mma16816(float* c, const uint32_t* a, const uint32_t* b) {
    asm volatile(
        "mma.sync.aligned.m16n8k16.row.col.f32.bf16.bf16.f32 "
        "{%0,%1,%2,%3}, {%4,%5,%6,%7}, {%8,%9}, {%0,%1,%2,%3};"
        : "+f"(c[0]), "+f"(c[1]), "+f"(c[2]), "+f"(c[3])
        : "r"(a[0]), "r"(a[1]), "r"(a[2]), "r"(a[3]), "r"(b[0]), "r"(b[1]));
}
__device__ __forceinline__ void ldsm4(uint32_t addr, uint32_t r[4]) {
    asm volatile("ldmatrix.sync.aligned.m8n8.x4.shared.b16 {%0,%1,%2,%3}, [%4];"
                 : "=r"(r[0]), "=r"(r[1]), "=r"(r[2]), "=r"(r[3]) : "r"(addr));
}
#define CP_ASYNC16(dst32, srcgen) \
    asm volatile("cp.async.cg.shared.global [%0], [%1], 16;" \
                 :: "r"(dst32), "l"(__cvta_generic_to_global(srcgen)) : "memory")
#define CP_COMMIT()  asm volatile("cp.async.commit_group;" ::: "memory")
#define CP_WAIT0()   asm volatile("cp.async.wait_group 0;" ::: "memory")

// ---------------------------------------------------------------------------
// k0: transpose + bf16-split W3  (grid 128 h x 2 k-halves)
// ---------------------------------------------------------------------------
__global__ void __launch_bounds__(256) k0_w3t(const float* __restrict__ W3) {
    float* s = reinterpret_cast<float*>(dynsm);     // [64][129]
    int h = blockIdx.x, zc = blockIdx.y, tid = threadIdx.x;
    for (int i = tid; i < 8192; i += 256) {
        int kk = i >> 7, f = i & 127;
        s[kk * 129 + f] = W3[(size_t)(zc * 64 + kk) * (DIN * DH) + h * DIN + f];
    }
    __syncthreads();
    for (int i = tid; i < 8192; i += 256) {
        int f = i >> 6, kk = i & 63;
        float v = s[kk * 129 + f];
        __nv_bfloat16 hi = __float2bfloat16(v);
        __nv_bfloat16 lo = __float2bfloat16(v - __bfloat162float(hi));
        size_t o = ((size_t)h * DIN + f) * DH + zc * 64 + kk;
        g_W3t_hi[o] = hi;
        g_W3t_lo[o] = lo;
    }
}

// ---------------------------------------------------------------------------
// k1: per-n fused 2-layer SIMT MLP -> g_h2 hi/lo
// ---------------------------------------------------------------------------
__device__ __forceinline__ void load_tile_transposed(float* As, const float* __restrict__ src, int tid) {
    #pragma unroll
    for (int i = tid; i < 4096; i += 256) {
        int l = i >> 5, k = (i & 31) << 2;
        float4 v = reinterpret_cast<const float4*>(src)[i];
        As[(k + 0) * PAD + l] = v.x;
        As[(k + 1) * PAD + l] = v.y;
        As[(k + 2) * PAD + l] = v.z;
        As[(k + 3) * PAD + l] = v.w;
    }
}
__device__ __forceinline__ void load_tile(float* Bs, const float* __restrict__ src, int stride, int tid) {
    #pragma unroll
    for (int i = tid; i < 4096; i += 256) {
        int r = i >> 5, c4 = i & 31;
        float4 v = reinterpret_cast<const float4*>(src + (size_t)r * stride)[c4];
        *reinterpret_cast<float4*>(&Bs[r * PAD + (c4 << 2)]) = v;
    }
}
__device__ __forceinline__ void gemm128(const float* As, const float* Bs, float acc[8][8], int tr, int tc) {
    #pragma unroll 4
    for (int k = 0; k < 128; ++k) {
        float4 a0 = *reinterpret_cast<const float4*>(&As[k * PAD + tr * 8]);
        float4 a1 = *reinterpret_cast<const float4*>(&As[k * PAD + tr * 8 + 4]);
        float4 b0 = *reinterpret_cast<const float4*>(&Bs[k * PAD + tc * 8]);
        float4 b1 = *reinterpret_cast<const float4*>(&Bs[k * PAD + tc * 8 + 4]);
        float a[8] = {a0.x, a0.y, a0.z, a0.w, a1.x, a1.y, a1.z, a1.w};
        float b[8] = {b0.x, b0.y, b0.z, b0.w, b1.x, b1.y, b1.z, b1.w};
        #pragma unroll
        for (int i = 0; i < 8; ++i)
            #pragma unroll
            for (int j = 0; j < 8; ++j)
                acc[i][j] = fmaf(a[i], b[j], acc[i][j]);
    }
}
__global__ void __launch_bounds__(256, 1) k1_mlp(
    const float* __restrict__ x,  const float* __restrict__ W1, const float* __restrict__ b1,
    const float* __restrict__ W2, const float* __restrict__ b2)
{
    float* As = reinterpret_cast<float*>(dynsm);
    float* Bs = As + 128 * PAD;
    int n = blockIdx.x, tid = threadIdx.x;
    int tr = tid & 15, tc = tid >> 4;

    load_tile_transposed(As, x + (size_t)n * LL * DIN, tid);
    load_tile(Bs, W1, DH, tid);
    __syncthreads();

    float acc[8][8];
    #pragma unroll
    for (int i = 0; i < 8; ++i)
        #pragma unroll
        for (int j = 0; j < 8; ++j) acc[i][j] = 0.0f;
    gemm128(As, Bs, acc, tr, tc);

    float bb[8];
    #pragma unroll
    for (int j = 0; j < 8; ++j) bb[j] = b1[tc * 8 + j];
    __syncthreads();

    #pragma unroll
    for (int i = 0; i < 8; ++i)
        #pragma unroll
        for (int j = 0; j < 8; ++j)
            As[(tc * 8 + j) * PAD + (tr * 8 + i)] = fmaxf(acc[i][j] + bb[j], 0.0f);
    load_tile(Bs, W2, DH, tid);
    __syncthreads();

    #pragma unroll
    for (int i = 0; i < 8; ++i)
        #pragma unroll
        for (int j = 0; j < 8; ++j) acc[i][j] = 0.0f;
    gemm128(As, Bs, acc, tr, tc);

    #pragma unroll
    for (int j = 0; j < 8; ++j) bb[j] = b2[tc * 8 + j];

    #pragma unroll
    for (int i = 0; i < 8; ++i) {
        int l = tr * 8 + i;
        size_t base = ((size_t)n * LL + l) * DH + tc * 8;
        #pragma unroll
        for (int j = 0; j < 8; ++j) {
            float v = fmaxf(acc[i][j] + bb[j], 0.0f);
            __nv_bfloat16 hi = __float2bfloat16(v);
            __nv_bfloat16 lo = __float2bfloat16(v - __bfloat162float(hi));
            g_h2hi[base + j] = hi;
            g_h2lo[base + j] = lo;
        }
    }
}

// ---------------------------------------------------------------------------
// k2: per-(hg,n) CTA. mma.sync split-bf16 + register epilogue + cp.async A.
// ---------------------------------------------------------------------------
#define OFF_A0   0
#define OFF_A1   69632
#define OFF_B    139264
#define OFF_IDX  208896      // 128 ints
#define OFF_LC   209408      // 1 int
#define OFF_SS   209424      // 256 f
#define OFF_DD   210448      // 256 f
#define OFF_RED  211472      // 8 f
#define K2_SMEM  211504

__device__ __forceinline__ void issue_A(uint32_t sb, int buf, int h, int tid) {
    uint32_t base = sb + (buf ? OFF_A1 : OFF_A0);
    const __nv_bfloat16* shi = g_W3t_hi + (size_t)h * DIN * DH;
    const __nv_bfloat16* slo = g_W3t_lo + (size_t)h * DIN * DH;
    #pragma unroll
    for (int i = tid; i < 4096; i += 256) {
        int plane = i >> 11, j = i & 2047;
        int r = j >> 4, c = j & 15;
        const __nv_bfloat16* src = (plane ? slo : shi) + r * 128 + c * 8;
        uint32_t dst = base + plane * APLANE + r * PITCHB + c * 16;
        CP_ASYNC16(dst, src);
    }
}

__global__ void __launch_bounds__(256, 1) k2_filter(
    const float* __restrict__ x, const float* __restrict__ mask,
    const float* __restrict__ tbias, float* __restrict__ out)
{
    char* sm = dynsm;
    const uint32_t sb = smem_u32(sm);
    int* sIdx = reinterpret_cast<int*>(sm + OFF_IDX);
    int* sLc  = reinterpret_cast<int*>(sm + OFF_LC);
    float* sS   = reinterpret_cast<float*>(sm + OFF_SS);
    float* sD   = reinterpret_cast<float*>(sm + OFF_DD);
    float* sRed = reinterpret_cast<float*>(sm + OFF_RED);

    const int tid  = threadIdx.x;
    const int lane = tid & 31, wid = tid >> 5;
    const int g = lane >> 2, tq = lane & 3;
    const int mh = wid & 3, nh = wid >> 2;
    const int f0 = mh * 32, l0 = nh * 64;
    const int n  = blockIdx.y, hg = blockIdx.x;
    const int h0 = hg * 64;

    // overlap: first A tile in flight during compaction + B load
    issue_A(sb, 0, h0, tid);
    CP_COMMIT();

    // mask compaction (warp 0)
    if (wid == 0) {
        int base = 0;
        #pragma unroll
        for (int c = 0; c < 4; ++c) {
            float mv = mask[n * LL + c * 32 + lane];
            unsigned bal = __ballot_sync(0xffffffffu, mv != 0.0f);
            int pos = __popc(bal & ((1u << lane) - 1u));
            if (mv != 0.0f) sIdx[base + pos] = c * 32 + lane;
            base += __popc(bal);
        }
        if (lane == 0) *sLc = base;
    }
    __syncthreads();
    const int Lc = *sLc;

    // B load (compacted rows, zero-fill tail)
    {
        const uint4* bhi = reinterpret_cast<const uint4*>(g_h2hi + (size_t)n * LL * DH);
        const uint4* blo = reinterpret_cast<const uint4*>(g_h2lo + (size_t)n * LL * DH);
        #pragma unroll
        for (int i = tid; i < 4096; i += 256) {
            int plane = i >> 11, j = i & 2047;
            int r = j >> 4, c = j & 15;
            uint4 v = make_uint4(0, 0, 0, 0);
            if (r < Lc) {
                int li = sIdx[r];
                v = (plane ? blo : bhi)[li * 16 + c];
            }
            *reinterpret_cast<uint4*>(sm + OFF_B + plane * APLANE + r * PITCHB + c * 16) = v;
        }
    }

    // x + validity into registers (tile-invariant across all 64 h!)
    float xr[4][16];
    float vf[16];
    {
        const float* xp = x + (size_t)n * LL * DIN;
        #pragma unroll
        for (int slot = 0; slot < 16; ++slot) {
            int nt = slot >> 1;
            int l  = l0 + nt * 8 + 2 * tq + (slot & 1);
            bool valid = l < Lc;
            vf[slot] = valid ? 1.0f : 0.0f;
            int li = valid ? sIdx[l] : 0;
            #pragma unroll
            for (int fr = 0; fr < 4; ++fr) {
                int f = f0 + (fr >> 1) * 16 + (fr & 1) * 8 + g;
                xr[fr][slot] = valid ? xp[li * DIN + f] : 0.0f;
            }
        }
    }
    __syncthreads();   // B ready for all

    // per-lane ldmatrix offsets
    const int rr = lane & 7, mm = lane >> 3;
    const uint32_t aoff = (uint32_t)((f0 + (mm & 1) * 8 + rr) * PITCHB + (mm >> 1) * 16);
    const uint32_t boff = (uint32_t)((l0 + (mm >> 1) * 8 + rr) * PITCHB + (mm & 1) * 16);
    const uint32_t aB = sb + OFF_B + boff;

    for (int hi = 0; hi < 64; ++hi) {
        CP_WAIT0();
        __syncthreads();
        const uint32_t aA = sb + ((hi & 1) ? OFF_A1 : OFF_A0) + aoff;

        float acc[2][8][4];
        #pragma unroll
        for (int mt = 0; mt < 2; ++mt)
            #pragma unroll
            for (int nt = 0; nt < 8; ++nt)
                #pragma unroll
                for (int q = 0; q < 4; ++q) acc[mt][nt][q] = 0.0f;

        #pragma unroll
        for (int ks = 0; ks < 8; ++ks) {
            const uint32_t ko = ks * 32;
            uint32_t ah[2][4], al[2][4];
            ldsm4(aA + ko,               ah[0]);
            ldsm4(aA + 4352 + ko,        ah[1]);
            ldsm4(aA + APLANE + ko,      al[0]);
            ldsm4(aA + APLANE + 4352 + ko, al[1]);
            #pragma unroll
            for (int p = 0; p < 4; ++p) {
                int lp = l0 + p * 16;
                if (lp < Lc) {
                    uint32_t bh[4], bl[4];
                    ldsm4(aB + p * 4352 + ko,          bh);
                    ldsm4(aB + APLANE + p * 4352 + ko, bl);
                    #pragma unroll
                    for (int mt = 0; mt < 2; ++mt) {
                        mma16816(acc[mt][2 * p], ah[mt], bh);
                        mma16816(acc[mt][2 * p], ah[mt], bl);
                        mma16816(acc[mt][2 * p], al[mt], bh);
                    }
                    if (lp + 8 < Lc) {
                        #pragma unroll
                        for (int mt = 0; mt < 2; ++mt) {
                            mma16816(acc[mt][2 * p + 1], ah[mt], bh + 2);
                            mma16816(acc[mt][2 * p + 1], ah[mt], bl + 2);
                            mma16816(acc[mt][2 * p + 1], al[mt], bh + 2);
                        }
                    }
                }
            }
        }

        // prefetch next A tile while epilogue runs
        if (hi < 63) {
            issue_A(sb, (hi + 1) & 1, h0 + hi + 1, tid);
            CP_COMMIT();
        }

        // register epilogue: per-f softmax sums + x contraction
        float s[4] = {0, 0, 0, 0}, d[4] = {0, 0, 0, 0};
        #pragma unroll
        for (int mt = 0; mt < 2; ++mt) {
            #pragma unroll
            for (int nt = 0; nt < 8; ++nt) {
                int s0 = nt * 2, s1 = nt * 2 + 1;
                int fr = mt * 2;
                float e0 = fexp(acc[mt][nt][0]) * vf[s0];
                float e1 = fexp(acc[mt][nt][1]) * vf[s1];
                float e2 = fexp(acc[mt][nt][2]) * vf[s0];
                float e3 = fexp(acc[mt][nt][3]) * vf[s1];
                s[fr]     += e0 + e1;
                s[fr + 1] += e2 + e3;
                d[fr]     = fmaf(xr[fr][s0], e0, d[fr]);
                d[fr]     = fmaf(xr[fr][s1], e1, d[fr]);
                d[fr + 1] = fmaf(xr[fr + 1][s0], e2, d[fr + 1]);
                d[fr + 1] = fmaf(xr[fr + 1][s1], e3, d[fr + 1]);
            }
        }
        #pragma unroll
        for (int fr = 0; fr < 4; ++fr) {
            s[fr] += __shfl_xor_sync(0xffffffffu, s[fr], 1);
            s[fr] += __shfl_xor_sync(0xffffffffu, s[fr], 2);
            d[fr] += __shfl_xor_sync(0xffffffffu, d[fr], 1);
            d[fr] += __shfl_xor_sync(0xffffffffu, d[fr], 2);
        }
        if (tq == 0) {
            #pragma unroll
            for (int fr = 0; fr < 4; ++fr) {
                sS[wid * 32 + fr * 8 + g] = s[fr];
                sD[wid * 32 + fr * 8 + g] = d[fr];
            }
        }
        __syncthreads();

        float r = 0.0f;
        if (tid < 128) {
            int f = tid;
            int i0 = (f >> 5) * 32 + ((f >> 3) & 3) * 8 + (f & 7);
            float ss = sS[i0] + sS[i0 + 128];
            float dd = sD[i0] + sD[i0 + 128];
            r = __fdividef(dd, ss);
        }
        #pragma unroll
        for (int o = 16; o; o >>= 1) r += __shfl_xor_sync(0xffffffffu, r, o);
        if (lane == 0) sRed[wid] = r;
        __syncthreads();
        if (tid == 0) {
            int h = h0 + hi;
            float t = sRed[0] + sRed[1] + sRed[2] + sRed[3];
            out[n * DH + h] = fmaxf(t + tbias[h], 0.0f);
        }
    }
}

// ---------------------------------------------------------------------------
extern "C" void kernel_launch(void* const* d_in, const int* in_sizes, int n_in,
                              void* d_out, int out_size) {
    const float* x    = (const float*)d_in[0];
    const float* mask = (const float*)d_in[1];
    const float* W1   = (const float*)d_in[2];
    const float* b1   = (const float*)d_in[3];
    const float* W2   = (const float*)d_in[4];
    const float* b2   = (const float*)d_in[5];
    const float* W3   = (const float*)d_in[6];
    // d_in[7] = b3: per-feature constant over l -> cancels in the softmax
    const float* tb   = (const float*)d_in[8];
    float* out = (float*)d_out;

    const int smem0 = 64 * 129 * (int)sizeof(float);
    const int smem1 = 2 * 128 * PAD * (int)sizeof(float);
    const int smem2 = K2_SMEM;

    cudaFuncSetAttribute(k0_w3t,    cudaFuncAttributeMaxDynamicSharedMemorySize, smem0);
    cudaFuncSetAttribute(k1_mlp,    cudaFuncAttributeMaxDynamicSharedMemorySize, smem1);
    cudaFuncSetAttribute(k2_filter, cudaFuncAttributeMaxDynamicSharedMemorySize, smem2);

    k0_w3t<<<dim3(DH, 2), 256, smem0>>>(W3);
    k1_mlp<<<NB, 256, smem1>>>(x, W1, b1, W2, b2);
    k2_filter<<<dim3(2, NB), 256, smem2>>>(x, mask, tb, out);
}

// round 8
// speedup vs baseline: 3.0404x; 1.0478x over previous
#include <cuda_runtime.h>
#include <cuda_bf16.h>
#include <cstdint>

#define NB   64
#define LL   128
#define DIN  128
#define DH   128
#define PITCHB 272      // bf16 tile row pitch in BYTES (136 bf16)
#define APLANE 34816    // 128*272

extern __shared__ char dynsm[];

__device__ __nv_bfloat16 g_W3t_hi[DH * DIN * DH];   // [h][f][k]
__device__ __nv_bfloat16 g_W3t_lo[DH * DIN * DH];
__device__ __nv_bfloat16 g_W1t_hi[DIN * DH];        // [j][k]
__device__ __nv_bfloat16 g_W1t_lo[DIN * DH];
__device__ __nv_bfloat16 g_W2t_hi[DH * DH];         // [k'][j]
__device__ __nv_bfloat16 g_W2t_lo[DH * DH];
__device__ __nv_bfloat16 g_h2hi[NB * LL * DH];      // [n][l][k]
__device__ __nv_bfloat16 g_h2lo[NB * LL * DH];

// ---------------------------------------------------------------------------
__device__ __forceinline__ uint32_t smem_u32(const void* p) {
    uint32_t a;
    asm("{ .reg .u64 t; cvta.to.shared.u64 t, %1; cvt.u32.u64 %0, t; }" : "=r"(a) : "l"(p));
    return a;
}
__device__ __forceinline__ float fexp(float a) {
    float t = fminf(fmaxf(a * 1.4426950408889634f, -126.0f), 126.0f);
    float k = rintf(t);
    float r = t - k;
    float p = 1.3333558e-3f;
    p = fmaf(p, r, 9.6181291e-3f);
    p = fmaf(p, r, 5.5504109e-2f);
    p = fmaf(p, r, 2.4022651e-1f);
    p = fmaf(p, r, 6.9314718e-1f);
    p = fmaf(p, r, 1.0f);
    return __int_as_float(((int)k + 127) << 23) * p;
}
__device__ __forceinline__ void mma16816(float* c, const uint32_t* a, const uint32_t* b) {
    asm volatile(
        "mma.sync.aligned.m16n8k16.row.col.f32.bf16.bf16.f32 "
        "{%0,%1,%2,%3}, {%4,%5,%6,%7}, {%8,%9}, {%0,%1,%2,%3};"
        : "+f"(c[0]), "+f"(c[1]), "+f"(c[2]), "+f"(c[3])
        : "r"(a[0]), "r"(a[1]), "r"(a[2]), "r"(a[3]), "r"(b[0]), "r"(b[1]));
}
__device__ __forceinline__ void ldsm4(uint32_t addr, uint32_t r[4]) {
    asm volatile("ldmatrix.sync.aligned.m8n8.x4.shared.b16 {%0,%1,%2,%3}, [%4];"
                 : "=r"(r[0]), "=r"(r[1]), "=r"(r[2]), "=r"(r[3]) : "r"(addr));
}
#define CP_ASYNC16(dst32, srcgen) \
    asm volatile("cp.async.cg.shared.global [%0], [%1], 16;" \
                 :: "r"(dst32), "l"(__cvta_generic_to_global(srcgen)) : "memory")
#define CP_COMMIT()  asm volatile("cp.async.commit_group;" ::: "memory")
#define CP_WAIT1()   asm volatile("cp.async.wait_group 1;" ::: "memory")

__device__ __forceinline__ uint32_t pack_bf2(float a, float b) {
    __nv_bfloat162 h = __floats2bfloat162_rn(a, b);
    return *reinterpret_cast<uint32_t*>(&h);
}

// ---------------------------------------------------------------------------
// k0: transpose + bf16-split W3 (bx<128), W1 (bx==128), W2 (bx==129)
// ---------------------------------------------------------------------------
__global__ void __launch_bounds__(256) k0_trans(
    const float* __restrict__ W3, const float* __restrict__ W1, const float* __restrict__ W2)
{
    float* s = reinterpret_cast<float*>(dynsm);   // [64][129]
    int bx = blockIdx.x, zc = blockIdx.y, tid = threadIdx.x;

    const float* src;
    size_t srcStride;
    __nv_bfloat16 *dhi, *dlo;
    if (bx < 128) {
        src = W3 + (size_t)(zc * 64) * (DIN * DH) + bx * DIN;
        srcStride = DIN * DH;
        dhi = g_W3t_hi + (size_t)bx * DIN * DH;
        dlo = g_W3t_lo + (size_t)bx * DIN * DH;
    } else if (bx == 128) {
        src = W1 + (size_t)(zc * 64) * DH;
        srcStride = DH;
        dhi = g_W1t_hi; dlo = g_W1t_lo;
    } else {
        src = W2 + (size_t)(zc * 64) * DH;
        srcStride = DH;
        dhi = g_W2t_hi; dlo = g_W2t_lo;
    }
    for (int i = tid; i < 8192; i += 256) {
        int kk = i >> 7, f = i & 127;
        s[kk * 129 + f] = src[(size_t)kk * srcStride + f];
    }
    __syncthreads();
    for (int i = tid; i < 8192; i += 256) {
        int f = i >> 6, kk = i & 63;
        float v = s[kk * 129 + f];
        __nv_bfloat16 hi = __float2bfloat16(v);
        __nv_bfloat16 lo = __float2bfloat16(v - __bfloat162float(hi));
        size_t o = (size_t)f * 128 + zc * 64 + kk;
        dhi[o] = hi;
        dlo[o] = lo;
    }
}

// ---------------------------------------------------------------------------
// k1: mma.sync split-bf16 2-layer MLP. grid 128 = (n, l-half). 256 thr.
// smem planes: P0/P1 = x hi/lo (64 rows) then h1 hi/lo; P2/P3 = W1t then W2t.
// ---------------------------------------------------------------------------
#define K1_P0   0
#define K1_P1   17408
#define K1_P2   34816
#define K1_P3   69632
#define K1_SMEM 104448

__global__ void __launch_bounds__(256, 1) k1_mlp(
    const float* __restrict__ x, const float* __restrict__ b1, const float* __restrict__ b2)
{
    char* sm = dynsm;
    const uint32_t sb = smem_u32(sm);
    const int tid = threadIdx.x;
    const int lane = tid & 31, wid = tid >> 5;
    const int g = lane >> 2, tq = lane & 3;
    const int jh = wid & 3, lw = wid >> 2;     // j0 = jh*32, l0w = lw*32
    const int j0 = jh * 32, l0w = lw * 32;
    const int n = blockIdx.x >> 1, lh = blockIdx.x & 1;

    // split x[n][lh*64 + r][*] into P0/P1 (pitch 272B)
    {
        const float* xp = x + ((size_t)n * LL + lh * 64) * DIN;
        for (int i = tid; i < 4096; i += 256) {
            int r = i >> 6, c2 = i & 63;           // col pair c2*2
            float2 v = reinterpret_cast<const float2*>(xp + (size_t)r * DIN)[c2];
            __nv_bfloat16 h0 = __float2bfloat16(v.x);
            __nv_bfloat16 h1 = __float2bfloat16(v.y);
            float r0 = v.x - __bfloat162float(h0);
            float r1 = v.y - __bfloat162float(h1);
            *reinterpret_cast<uint32_t*>(sm + K1_P0 + r * PITCHB + c2 * 4) =
                ((uint32_t)*reinterpret_cast<uint16_t*>(&h0)) |
                ((uint32_t)*reinterpret_cast<uint16_t*>(&h1) << 16);
            *reinterpret_cast<uint32_t*>(sm + K1_P1 + r * PITCHB + c2 * 4) = pack_bf2(r0, r1);
        }
    }
    // load W1t planes
    for (int i = tid; i < 4096; i += 256) {
        int pl = i >> 11, j = i & 2047;
        int r = j >> 4, c = j & 15;
        const __nv_bfloat16* src = (pl ? g_W1t_lo : g_W1t_hi) + r * 128 + c * 8;
        *reinterpret_cast<uint4*>(sm + K1_P2 + pl * APLANE + r * PITCHB + c * 16) =
            *reinterpret_cast<const uint4*>(src);
    }
    __syncthreads();

    const int rr = lane & 7, mm = lane >> 3;
    const uint32_t aoffA = (uint32_t)((l0w + (mm & 1) * 8 + rr) * PITCHB + (mm >> 1) * 16);
    const uint32_t aoffB = (uint32_t)((j0 + (mm >> 1) * 8 + rr) * PITCHB + (mm & 1) * 16);

    // ---- GEMM1: h1[l, j] = relu(x @ W1 + b1)
    float acc[2][4][4];
    #pragma unroll
    for (int mt = 0; mt < 2; ++mt)
        #pragma unroll
        for (int nt = 0; nt < 4; ++nt)
            #pragma unroll
            for (int q = 0; q < 4; ++q) acc[mt][nt][q] = 0.0f;

    {
        const uint32_t aA = sb + K1_P0 + aoffA;
        const uint32_t aB = sb + K1_P2 + aoffB;
        #pragma unroll
        for (int ks = 0; ks < 8; ++ks) {
            const uint32_t ko = ks * 32;
            uint32_t ah[2][4], al[2][4];
            ldsm4(aA + ko, ah[0]);
            ldsm4(aA + 4352 + ko, ah[1]);
            ldsm4(aA + 17408 + ko, al[0]);
            ldsm4(aA + 17408 + 4352 + ko, al[1]);
            #pragma unroll
            for (int p = 0; p < 2; ++p) {
                uint32_t bh[4], bl[4];
                ldsm4(aB + p * 4352 + ko, bh);
                ldsm4(aB + APLANE + p * 4352 + ko, bl);
                #pragma unroll
                for (int mt = 0; mt < 2; ++mt) {
                    mma16816(acc[mt][2 * p], ah[mt], bh);
                    mma16816(acc[mt][2 * p], ah[mt], bl);
                    mma16816(acc[mt][2 * p], al[mt], bh);
                    mma16816(acc[mt][2 * p + 1], ah[mt], bh + 2);
                    mma16816(acc[mt][2 * p + 1], ah[mt], bl + 2);
                    mma16816(acc[mt][2 * p + 1], al[mt], bh + 2);
                }
            }
        }
    }
    __syncthreads();   // all GEMM1 reads of P0..P3 complete

    // bias + relu + split, store h1 into P0/P1 as [l][j]
    {
        float bv[8];
        #pragma unroll
        for (int nt = 0; nt < 4; ++nt) {
            bv[nt * 2]     = b1[j0 + nt * 8 + 2 * tq];
            bv[nt * 2 + 1] = b1[j0 + nt * 8 + 2 * tq + 1];
        }
        #pragma unroll
        for (int mt = 0; mt < 2; ++mt)
            #pragma unroll
            for (int nt = 0; nt < 4; ++nt) {
                int col = j0 + nt * 8 + 2 * tq;
                int row0 = l0w + mt * 16 + g;
                float v0 = fmaxf(acc[mt][nt][0] + bv[nt * 2], 0.0f);
                float v1 = fmaxf(acc[mt][nt][1] + bv[nt * 2 + 1], 0.0f);
                float v2 = fmaxf(acc[mt][nt][2] + bv[nt * 2], 0.0f);
                float v3 = fmaxf(acc[mt][nt][3] + bv[nt * 2 + 1], 0.0f);
                __nv_bfloat16 h0 = __float2bfloat16(v0), h1 = __float2bfloat16(v1);
                __nv_bfloat16 h2 = __float2bfloat16(v2), h3 = __float2bfloat16(v3);
                uint32_t hp0 = ((uint32_t)*reinterpret_cast<uint16_t*>(&h0)) |
                               ((uint32_t)*reinterpret_cast<uint16_t*>(&h1) << 16);
                uint32_t hp1 = ((uint32_t)*reinterpret_cast<uint16_t*>(&h2)) |
                               ((uint32_t)*reinterpret_cast<uint16_t*>(&h3) << 16);
                *reinterpret_cast<uint32_t*>(sm + K1_P0 + row0 * PITCHB + col * 2) = hp0;
                *reinterpret_cast<uint32_t*>(sm + K1_P0 + (row0 + 8) * PITCHB + col * 2) = hp1;
                *reinterpret_cast<uint32_t*>(sm + K1_P1 + row0 * PITCHB + col * 2) =
                    pack_bf2(v0 - __bfloat162float(h0), v1 - __bfloat162float(h1));
                *reinterpret_cast<uint32_t*>(sm + K1_P1 + (row0 + 8) * PITCHB + col * 2) =
                    pack_bf2(v2 - __bfloat162float(h2), v3 - __bfloat162float(h3));
            }
    }
    // load W2t over W1t
    for (int i = tid; i < 4096; i += 256) {
        int pl = i >> 11, j = i & 2047;
        int r = j >> 4, c = j & 15;
        const __nv_bfloat16* src = (pl ? g_W2t_lo : g_W2t_hi) + r * 128 + c * 8;
        *reinterpret_cast<uint4*>(sm + K1_P2 + pl * APLANE + r * PITCHB + c * 16) =
            *reinterpret_cast<const uint4*>(src);
    }
    __syncthreads();

    // ---- GEMM2: h2[l, k'] = relu(h1 @ W2 + b2)
    #pragma unroll
    for (int mt = 0; mt < 2; ++mt)
        #pragma unroll
        for (int nt = 0; nt < 4; ++nt)
            #pragma unroll
            for (int q = 0; q < 4; ++q) acc[mt][nt][q] = 0.0f;
    {
        const uint32_t aA = sb + K1_P0 + aoffA;
        const uint32_t aB = sb + K1_P2 + aoffB;
        #pragma unroll
        for (int ks = 0; ks < 8; ++ks) {
            const uint32_t ko = ks * 32;
            uint32_t ah[2][4], al[2][4];
            ldsm4(aA + ko, ah[0]);
            ldsm4(aA + 4352 + ko, ah[1]);
            ldsm4(aA + 17408 + ko, al[0]);
            ldsm4(aA + 17408 + 4352 + ko, al[1]);
            #pragma unroll
            for (int p = 0; p < 2; ++p) {
                uint32_t bh[4], bl[4];
                ldsm4(aB + p * 4352 + ko, bh);
                ldsm4(aB + APLANE + p * 4352 + ko, bl);
                #pragma unroll
                for (int mt = 0; mt < 2; ++mt) {
                    mma16816(acc[mt][2 * p], ah[mt], bh);
                    mma16816(acc[mt][2 * p], ah[mt], bl);
                    mma16816(acc[mt][2 * p], al[mt], bh);
                    mma16816(acc[mt][2 * p + 1], ah[mt], bh + 2);
                    mma16816(acc[mt][2 * p + 1], ah[mt], bl + 2);
                    mma16816(acc[mt][2 * p + 1], al[mt], bh + 2);
                }
            }
        }
    }
    // bias + relu + split, store to global
    {
        float bv[8];
        #pragma unroll
        for (int nt = 0; nt < 4; ++nt) {
            bv[nt * 2]     = b2[j0 + nt * 8 + 2 * tq];
            bv[nt * 2 + 1] = b2[j0 + nt * 8 + 2 * tq + 1];
        }
        size_t rowg0 = (size_t)n * LL + lh * 64;
        #pragma unroll
        for (int mt = 0; mt < 2; ++mt)
            #pragma unroll
            for (int nt = 0; nt < 4; ++nt) {
                int col = j0 + nt * 8 + 2 * tq;
                size_t row0 = rowg0 + l0w + mt * 16 + g;
                float v0 = fmaxf(acc[mt][nt][0] + bv[nt * 2], 0.0f);
                float v1 = fmaxf(acc[mt][nt][1] + bv[nt * 2 + 1], 0.0f);
                float v2 = fmaxf(acc[mt][nt][2] + bv[nt * 2], 0.0f);
                float v3 = fmaxf(acc[mt][nt][3] + bv[nt * 2 + 1], 0.0f);
                __nv_bfloat16 h0 = __float2bfloat16(v0), h1 = __float2bfloat16(v1);
                __nv_bfloat16 h2 = __float2bfloat16(v2), h3 = __float2bfloat16(v3);
                *reinterpret_cast<uint32_t*>(&g_h2hi[row0 * DH + col]) =
                    ((uint32_t)*reinterpret_cast<uint16_t*>(&h0)) |
                    ((uint32_t)*reinterpret_cast<uint16_t*>(&h1) << 16);
                *reinterpret_cast<uint32_t*>(&g_h2hi[(row0 + 8) * DH + col]) =
                    ((uint32_t)*reinterpret_cast<uint16_t*>(&h2)) |
                    ((uint32_t)*reinterpret_cast<uint16_t*>(&h3) << 16);
                *reinterpret_cast<uint32_t*>(&g_h2lo[row0 * DH + col]) =
                    pack_bf2(v0 - __bfloat162float(h0), v1 - __bfloat162float(h1));
                *reinterpret_cast<uint32_t*>(&g_h2lo[(row0 + 8) * DH + col]) =
                    pack_bf2(v2 - __bfloat162float(h2), v3 - __bfloat162float(h3));
            }
    }
}

// ---------------------------------------------------------------------------
// k2: persistent (148 CTAs), balanced static ranges over 8192 (n,h) tiles.
// ---------------------------------------------------------------------------
#define OFF_A0   0
#define OFF_A1   69632
#define OFF_B    139264
#define OFF_IDX  208896      // 128 ints
#define OFF_LC   209408
#define OFF_SS   209424      // 256 f
#define OFF_DD   210448      // 256 f
#define K2_SMEM  211472

#define NCTA 148
#define NTILES 8192

__device__ __forceinline__ void issue_A(uint32_t sb, int buf, int h, int tid) {
    uint32_t base = sb + (buf ? OFF_A1 : OFF_A0);
    const __nv_bfloat16* shi = g_W3t_hi + (size_t)h * DIN * DH;
    const __nv_bfloat16* slo = g_W3t_lo + (size_t)h * DIN * DH;
    #pragma unroll
    for (int i = tid; i < 4096; i += 256) {
        int plane = i >> 11, j = i & 2047;
        int r = j >> 4, c = j & 15;
        const __nv_bfloat16* src = (plane ? slo : shi) + r * 128 + c * 8;
        CP_ASYNC16(base + plane * APLANE + r * PITCHB + c * 16, src);
    }
}

__global__ void __launch_bounds__(256, 1) k2_filter(
    const float* __restrict__ x, const float* __restrict__ mask,
    const float* __restrict__ tbias, float* __restrict__ out)
{
    char* sm = dynsm;
    const uint32_t sb = smem_u32(sm);
    int* sIdx = reinterpret_cast<int*>(sm + OFF_IDX);
    int* sLc  = reinterpret_cast<int*>(sm + OFF_LC);
    float* sS = reinterpret_cast<float*>(sm + OFF_SS);
    float* sD = reinterpret_cast<float*>(sm + OFF_DD);

    const int tid  = threadIdx.x;
    const int lane = tid & 31, wid = tid >> 5;
    const int g = lane >> 2, tq = lane & 3;
    const int mh = wid & 3, nh = wid >> 2;
    const int f0 = mh * 32, l0 = nh * 64;

    const int c  = blockIdx.x;
    const int ts = (c * NTILES) / NCTA;
    const int te = ((c + 1) * NTILES) / NCTA;

    const int rr = lane & 7, mm = lane >> 3;
    const uint32_t aoff = (uint32_t)((f0 + (mm & 1) * 8 + rr) * PITCHB + (mm >> 1) * 16);
    const uint32_t boff = (uint32_t)((l0 + (mm >> 1) * 8 + rr) * PITCHB + (mm & 1) * 16);
    const uint32_t aB = sb + OFF_B + boff;

    // prologue: first A tile in flight
    issue_A(sb, 0, ts & 127, tid);
    CP_COMMIT();

    int curn = -1, buf = 0, Lc = 0;
    float xr[4][16], vf[16];

    for (int t = ts; t < te; ++t) {
        const int n = t >> 7, h = t & 127;

        if (n != curn) {
            curn = n;
            // compaction (warp 0). Prev-tile MMAs (if any) are done: two syncs ago.
            if (wid == 0) {
                int base = 0;
                #pragma unroll
                for (int cc = 0; cc < 4; ++cc) {
                    float mv = mask[n * LL + cc * 32 + lane];
                    unsigned bal = __ballot_sync(0xffffffffu, mv != 0.0f);
                    int pos = __popc(bal & ((1u << lane) - 1u));
                    if (mv != 0.0f) sIdx[base + pos] = cc * 32 + lane;
                    base += __popc(bal);
                }
                if (lane == 0) *sLc = base;
            }
            __syncthreads();
            Lc = *sLc;
            // B load (compacted rows, zero tail)
            {
                const uint4* bhi = reinterpret_cast<const uint4*>(g_h2hi + (size_t)n * LL * DH);
                const uint4* blo = reinterpret_cast<const uint4*>(g_h2lo + (size_t)n * LL * DH);
                #pragma unroll
                for (int i = tid; i < 4096; i += 256) {
                    int plane = i >> 11, j = i & 2047;
                    int r = j >> 4, cc = j & 15;
                    uint4 v = make_uint4(0, 0, 0, 0);
                    if (r < Lc) v = (plane ? blo : bhi)[sIdx[r] * 16 + cc];
                    *reinterpret_cast<uint4*>(sm + OFF_B + plane * APLANE + r * PITCHB + cc * 16) = v;
                }
            }
            // x + validity registers
            {
                const float* xp = x + (size_t)n * LL * DIN;
                #pragma unroll
                for (int slot = 0; slot < 16; ++slot) {
                    int nt = slot >> 1;
                    int l  = l0 + nt * 8 + 2 * tq + (slot & 1);
                    bool valid = l < Lc;
                    vf[slot] = valid ? 1.0f : 0.0f;
                    int li = valid ? sIdx[l] : 0;
                    #pragma unroll
                    for (int fr = 0; fr < 4; ++fr) {
                        int f = f0 + (fr >> 1) * 16 + (fr & 1) * 8 + g;
                        xr[fr][slot] = valid ? xp[(size_t)li * DIN + f] : 0.0f;
                    }
                }
            }
        }

        // prefetch next A; then wait for current A (1 group pending = next)
        if (t + 1 < te) issue_A(sb, buf ^ 1, (t + 1) & 127, tid);
        CP_COMMIT();
        CP_WAIT1();
        __syncthreads();   // SYNC_A: A(t) + (on switch) B visible to all

        const uint32_t aA = sb + (buf ? OFF_A1 : OFF_A0) + aoff;

        float acc[2][8][4];
        #pragma unroll
        for (int mt = 0; mt < 2; ++mt)
            #pragma unroll
            for (int nt = 0; nt < 8; ++nt)
                #pragma unroll
                for (int q = 0; q < 4; ++q) acc[mt][nt][q] = 0.0f;

        #pragma unroll
        for (int ks = 0; ks < 8; ++ks) {
            const uint32_t ko = ks * 32;
            uint32_t ah[2][4], al[2][4];
            ldsm4(aA + ko, ah[0]);
            ldsm4(aA + 4352 + ko, ah[1]);
            ldsm4(aA + APLANE + ko, al[0]);
            ldsm4(aA + APLANE + 4352 + ko, al[1]);
            #pragma unroll
            for (int p = 0; p < 4; ++p) {
                int lp = l0 + p * 16;
                if (lp < Lc) {
                    uint32_t bh[4], bl[4];
                    ldsm4(aB + p * 4352 + ko, bh);
                    ldsm4(aB + APLANE + p * 4352 + ko, bl);
                    #pragma unroll
                    for (int mt = 0; mt < 2; ++mt) {
                        mma16816(acc[mt][2 * p], ah[mt], bh);
                        mma16816(acc[mt][2 * p], ah[mt], bl);
                        mma16816(acc[mt][2 * p], al[mt], bh);
                    }
                    if (lp + 8 < Lc) {
                        #pragma unroll
                        for (int mt = 0; mt < 2; ++mt) {
                            mma16816(acc[mt][2 * p + 1], ah[mt], bh + 2);
                            mma16816(acc[mt][2 * p + 1], ah[mt], bl + 2);
                            mma16816(acc[mt][2 * p + 1], al[mt], bh + 2);
                        }
                    }
                }
            }
        }
        buf ^= 1;

        // register epilogue
        float s[4] = {0, 0, 0, 0}, d[4] = {0, 0, 0, 0};
        #pragma unroll
        for (int mt = 0; mt < 2; ++mt)
            #pragma unroll
            for (int nt = 0; nt < 8; ++nt) {
                int s0 = nt * 2, s1 = nt * 2 + 1;
                int fr = mt * 2;
                float e0 = fexp(acc[mt][nt][0]) * vf[s0];
                float e1 = fexp(acc[mt][nt][1]) * vf[s1];
                float e2 = fexp(acc[mt][nt][2]) * vf[s0];
                float e3 = fexp(acc[mt][nt][3]) * vf[s1];
                s[fr]     += e0 + e1;
                s[fr + 1] += e2 + e3;
                d[fr]     = fmaf(xr[fr][s0], e0, d[fr]);
                d[fr]     = fmaf(xr[fr][s1], e1, d[fr]);
                d[fr + 1] = fmaf(xr[fr + 1][s0], e2, d[fr + 1]);
                d[fr + 1] = fmaf(xr[fr + 1][s1], e3, d[fr + 1]);
            }
        #pragma unroll
        for (int fr = 0; fr < 4; ++fr) {
            s[fr] += __shfl_xor_sync(0xffffffffu, s[fr], 1);
            s[fr] += __shfl_xor_sync(0xffffffffu, s[fr], 2);
            d[fr] += __shfl_xor_sync(0xffffffffu, d[fr], 1);
            d[fr] += __shfl_xor_sync(0xffffffffu, d[fr], 2);
        }
        __syncthreads();   // SYNC1: all MMAs done (next issue safe) + prev warp0 reads done
        if (tq == 0) {
            #pragma unroll
            for (int fr = 0; fr < 4; ++fr) {
                sS[wid * 32 + fr * 8 + g] = s[fr];
                sD[wid * 32 + fr * 8 + g] = d[fr];
            }
        }
        __syncthreads();   // SYNC2
        if (wid == 0) {
            float r = 0.0f;
            #pragma unroll
            for (int q = 0; q < 4; ++q) {
                int f = lane + q * 32;
                int i0 = (f >> 5) * 32 + ((f >> 3) & 3) * 8 + (f & 7);
                float ss = sS[i0] + sS[i0 + 128];
                float dd = sD[i0] + sD[i0 + 128];
                r += __fdividef(dd, ss);
            }
            #pragma unroll
            for (int o = 16; o; o >>= 1) r += __shfl_xor_sync(0xffffffffu, r, o);
            if (lane == 0)
                out[n * DH + h] = fmaxf(r + tbias[h], 0.0f);
        }
    }
}

// ---------------------------------------------------------------------------
extern "C" void kernel_launch(void* const* d_in, const int* in_sizes, int n_in,
                              void* d_out, int out_size) {
    const float* x    = (const float*)d_in[0];
    const float* mask = (const float*)d_in[1];
    const float* W1   = (const float*)d_in[2];
    const float* b1   = (const float*)d_in[3];
    const float* W2   = (const float*)d_in[4];
    const float* b2   = (const float*)d_in[5];
    const float* W3   = (const float*)d_in[6];
    // d_in[7] = b3: per-feature constant over l -> cancels in the softmax
    const float* tb   = (const float*)d_in[8];
    float* out = (float*)d_out;

    const int smem0 = 64 * 129 * (int)sizeof(float);
    const int smem1 = K1_SMEM;
    const int smem2 = K2_SMEM;

    cudaFuncSetAttribute(k0_trans,  cudaFuncAttributeMaxDynamicSharedMemorySize, smem0);
    cudaFuncSetAttribute(k1_mlp,    cudaFuncAttributeMaxDynamicSharedMemorySize, smem1);
    cudaFuncSetAttribute(k2_filter, cudaFuncAttributeMaxDynamicSharedMemorySize, smem2);

    k0_trans<<<dim3(130, 2), 256, smem0>>>(W3, W1, W2);
    k1_mlp<<<NB * 2, 256, smem1>>>(x, b1, b2);
    k2_filter<<<NCTA, 256, smem2>>>(x, mask, tb, out);
}

// round 9
// speedup vs baseline: 6.9763x; 2.2945x over previous
#include <cuda_runtime.h>
#include <cuda_bf16.h>
#include <cuda_fp16.h>
#include <cstdint>

#define NB   64
#define LL   128
#define DIN  128
#define DH   128
#define PITCHB 272      // b16 tile row pitch in BYTES (136 elems)
#define APLANE 34816    // 128*272

extern __shared__ char dynsm[];

__device__ __half        g_W3f16[DH * DIN * DH];    // [h][f][k]
__device__ __nv_bfloat16 g_W1t_hi[DIN * DH];        // [j][k]
__device__ __nv_bfloat16 g_W1t_lo[DIN * DH];
__device__ __nv_bfloat16 g_W2t_hi[DH * DH];         // [k'][j]
__device__ __nv_bfloat16 g_W2t_lo[DH * DH];
__device__ __half        g_h2f16[NB * LL * DH];     // [n][l][k]

// ---------------------------------------------------------------------------
__device__ __forceinline__ uint32_t smem_u32(const void* p) {
    uint32_t a;
    asm("{ .reg .u64 t; cvta.to.shared.u64 t, %1; cvt.u32.u64 %0, t; }" : "=r"(a) : "l"(p));
    return a;
}
__device__ __forceinline__ void mma16816bf(float* c, const uint32_t* a, const uint32_t* b) {
    asm volatile(
        "mma.sync.aligned.m16n8k16.row.col.f32.bf16.bf16.f32 "
        "{%0,%1,%2,%3}, {%4,%5,%6,%7}, {%8,%9}, {%0,%1,%2,%3};"
        : "+f"(c[0]), "+f"(c[1]), "+f"(c[2]), "+f"(c[3])
        : "r"(a[0]), "r"(a[1]), "r"(a[2]), "r"(a[3]), "r"(b[0]), "r"(b[1]));
}
__device__ __forceinline__ void mma16816h(float* c, const uint32_t* a, const uint32_t* b) {
    asm volatile(
        "mma.sync.aligned.m16n8k16.row.col.f32.f16.f16.f32 "
        "{%0,%1,%2,%3}, {%4,%5,%6,%7}, {%8,%9}, {%0,%1,%2,%3};"
        : "+f"(c[0]), "+f"(c[1]), "+f"(c[2]), "+f"(c[3])
        : "r"(a[0]), "r"(a[1]), "r"(a[2]), "r"(a[3]), "r"(b[0]), "r"(b[1]));
}
__device__ __forceinline__ void ldsm4(uint32_t addr, uint32_t r[4]) {
    asm volatile("ldmatrix.sync.aligned.m8n8.x4.shared.b16 {%0,%1,%2,%3}, [%4];"
                 : "=r"(r[0]), "=r"(r[1]), "=r"(r[2]), "=r"(r[3]) : "r"(addr));
}
#define CP_ASYNC16(dst32, srcgen) \
    asm volatile("cp.async.cg.shared.global [%0], [%1], 16;" \
                 :: "r"(dst32), "l"(__cvta_generic_to_global(srcgen)) : "memory")
#define CP_COMMIT()  asm volatile("cp.async.commit_group;" ::: "memory")
#define CP_WAIT1()   asm volatile("cp.async.wait_group 1;" ::: "memory")

__device__ __forceinline__ uint32_t pack_bf2(float a, float b) {
    __nv_bfloat162 h = __floats2bfloat162_rn(a, b);
    return *reinterpret_cast<uint32_t*>(&h);
}
__device__ __forceinline__ uint32_t pack_h2(float a, float b) {
    __half2 h = __floats2half2_rn(a, b);
    return *reinterpret_cast<uint32_t*>(&h);
}

// ---------------------------------------------------------------------------
// k0: W3 -> fp16 [h][f][k] (bx<128); W1 (bx==128), W2 (bx==129) -> bf16 split
// ---------------------------------------------------------------------------
__global__ void __launch_bounds__(256) k0_trans(
    const float* __restrict__ W3, const float* __restrict__ W1, const float* __restrict__ W2)
{
    float* s = reinterpret_cast<float*>(dynsm);   // [64][129]
    int bx = blockIdx.x, zc = blockIdx.y, tid = threadIdx.x;

    if (bx < 128) {
        const float* src = W3 + (size_t)(zc * 64) * (DIN * DH) + bx * DIN;
        for (int i = tid; i < 8192; i += 256) {
            int kk = i >> 7, f = i & 127;
            s[kk * 129 + f] = src[(size_t)kk * (DIN * DH) + f];
        }
        __syncthreads();
        __half* dst = g_W3f16 + (size_t)bx * DIN * DH;
        for (int i = tid; i < 8192; i += 256) {
            int f = i >> 6, kk = i & 63;
            dst[(size_t)f * 128 + zc * 64 + kk] = __float2half(s[kk * 129 + f]);
        }
    } else {
        const float* src = (bx == 128 ? W1 : W2) + (size_t)(zc * 64) * DH;
        __nv_bfloat16* dhi = (bx == 128) ? g_W1t_hi : g_W2t_hi;
        __nv_bfloat16* dlo = (bx == 128) ? g_W1t_lo : g_W2t_lo;
        for (int i = tid; i < 8192; i += 256) {
            int kk = i >> 7, f = i & 127;
            s[kk * 129 + f] = src[(size_t)kk * DH + f];
        }
        __syncthreads();
        for (int i = tid; i < 8192; i += 256) {
            int f = i >> 6, kk = i & 63;
            float v = s[kk * 129 + f];
            __nv_bfloat16 hi = __float2bfloat16(v);
            __nv_bfloat16 lo = __float2bfloat16(v - __bfloat162float(hi));
            size_t o = (size_t)f * 128 + zc * 64 + kk;
            dhi[o] = hi;
            dlo[o] = lo;
        }
    }
}

// ---------------------------------------------------------------------------
// k1: mma.sync split-bf16 2-layer MLP. grid 128 = (n, l-half). 256 thr.
// Internally split-bf16 for accuracy; OUTPUT h2 as fp16 single plane.
// ---------------------------------------------------------------------------
#define K1_P0   0
#define K1_P1   17408
#define K1_P2   34816
#define K1_SMEM 104448

__global__ void __launch_bounds__(256, 1) k1_mlp(
    const float* __restrict__ x, const float* __restrict__ b1, const float* __restrict__ b2)
{
    char* sm = dynsm;
    const uint32_t sb = smem_u32(sm);
    const int tid = threadIdx.x;
    const int lane = tid & 31, wid = tid >> 5;
    const int g = lane >> 2, tq = lane & 3;
    const int jh = wid & 3, lw = wid >> 2;
    const int j0 = jh * 32, l0w = lw * 32;
    const int n = blockIdx.x >> 1, lh = blockIdx.x & 1;

    {
        const float* xp = x + ((size_t)n * LL + lh * 64) * DIN;
        for (int i = tid; i < 4096; i += 256) {
            int r = i >> 6, c2 = i & 63;
            float2 v = reinterpret_cast<const float2*>(xp + (size_t)r * DIN)[c2];
            __nv_bfloat16 h0 = __float2bfloat16(v.x);
            __nv_bfloat16 h1 = __float2bfloat16(v.y);
            *reinterpret_cast<uint32_t*>(sm + K1_P0 + r * PITCHB + c2 * 4) =
                ((uint32_t)*reinterpret_cast<uint16_t*>(&h0)) |
                ((uint32_t)*reinterpret_cast<uint16_t*>(&h1) << 16);
            *reinterpret_cast<uint32_t*>(sm + K1_P1 + r * PITCHB + c2 * 4) =
                pack_bf2(v.x - __bfloat162float(h0), v.y - __bfloat162float(h1));
        }
    }
    for (int i = tid; i < 4096; i += 256) {
        int pl = i >> 11, j = i & 2047;
        int r = j >> 4, c = j & 15;
        const __nv_bfloat16* src = (pl ? g_W1t_lo : g_W1t_hi) + r * 128 + c * 8;
        *reinterpret_cast<uint4*>(sm + K1_P2 + pl * APLANE + r * PITCHB + c * 16) =
            *reinterpret_cast<const uint4*>(src);
    }
    __syncthreads();

    const int rr = lane & 7, mm = lane >> 3;
    const uint32_t aoffA = (uint32_t)((l0w + (mm & 1) * 8 + rr) * PITCHB + (mm >> 1) * 16);
    const uint32_t aoffB = (uint32_t)((j0 + (mm >> 1) * 8 + rr) * PITCHB + (mm & 1) * 16);

    float acc[2][4][4];
    #pragma unroll
    for (int mt = 0; mt < 2; ++mt)
        #pragma unroll
        for (int nt = 0; nt < 4; ++nt)
            #pragma unroll
            for (int q = 0; q < 4; ++q) acc[mt][nt][q] = 0.0f;

    {
        const uint32_t aA = sb + K1_P0 + aoffA;
        const uint32_t aB = sb + K1_P2 + aoffB;
        #pragma unroll
        for (int ks = 0; ks < 8; ++ks) {
            const uint32_t ko = ks * 32;
            uint32_t ah[2][4], al[2][4];
            ldsm4(aA + ko, ah[0]);
            ldsm4(aA + 4352 + ko, ah[1]);
            ldsm4(aA + 17408 + ko, al[0]);
            ldsm4(aA + 17408 + 4352 + ko, al[1]);
            #pragma unroll
            for (int p = 0; p < 2; ++p) {
                uint32_t bh[4], bl[4];
                ldsm4(aB + p * 4352 + ko, bh);
                ldsm4(aB + APLANE + p * 4352 + ko, bl);
                #pragma unroll
                for (int mt = 0; mt < 2; ++mt) {
                    mma16816bf(acc[mt][2 * p], ah[mt], bh);
                    mma16816bf(acc[mt][2 * p], ah[mt], bl);
                    mma16816bf(acc[mt][2 * p], al[mt], bh);
                    mma16816bf(acc[mt][2 * p + 1], ah[mt], bh + 2);
                    mma16816bf(acc[mt][2 * p + 1], ah[mt], bl + 2);
                    mma16816bf(acc[mt][2 * p + 1], al[mt], bh + 2);
                }
            }
        }
    }
    __syncthreads();

    {
        float bv[8];
        #pragma unroll
        for (int nt = 0; nt < 4; ++nt) {
            bv[nt * 2]     = b1[j0 + nt * 8 + 2 * tq];
            bv[nt * 2 + 1] = b1[j0 + nt * 8 + 2 * tq + 1];
        }
        #pragma unroll
        for (int mt = 0; mt < 2; ++mt)
            #pragma unroll
            for (int nt = 0; nt < 4; ++nt) {
                int col = j0 + nt * 8 + 2 * tq;
                int row0 = l0w + mt * 16 + g;
                float v0 = fmaxf(acc[mt][nt][0] + bv[nt * 2], 0.0f);
                float v1 = fmaxf(acc[mt][nt][1] + bv[nt * 2 + 1], 0.0f);
                float v2 = fmaxf(acc[mt][nt][2] + bv[nt * 2], 0.0f);
                float v3 = fmaxf(acc[mt][nt][3] + bv[nt * 2 + 1], 0.0f);
                __nv_bfloat16 h0 = __float2bfloat16(v0), h1 = __float2bfloat16(v1);
                __nv_bfloat16 h2 = __float2bfloat16(v2), h3 = __float2bfloat16(v3);
                *reinterpret_cast<uint32_t*>(sm + K1_P0 + row0 * PITCHB + col * 2) =
                    ((uint32_t)*reinterpret_cast<uint16_t*>(&h0)) |
                    ((uint32_t)*reinterpret_cast<uint16_t*>(&h1) << 16);
                *reinterpret_cast<uint32_t*>(sm + K1_P0 + (row0 + 8) * PITCHB + col * 2) =
                    ((uint32_t)*reinterpret_cast<uint16_t*>(&h2)) |
                    ((uint32_t)*reinterpret_cast<uint16_t*>(&h3) << 16);
                *reinterpret_cast<uint32_t*>(sm + K1_P1 + row0 * PITCHB + col * 2) =
                    pack_bf2(v0 - __bfloat162float(h0), v1 - __bfloat162float(h1));
                *reinterpret_cast<uint32_t*>(sm + K1_P1 + (row0 + 8) * PITCHB + col * 2) =
                    pack_bf2(v2 - __bfloat162float(h2), v3 - __bfloat162float(h3));
            }
    }
    for (int i = tid; i < 4096; i += 256) {
        int pl = i >> 11, j = i & 2047;
        int r = j >> 4, c = j & 15;
        const __nv_bfloat16* src = (pl ? g_W2t_lo : g_W2t_hi) + r * 128 + c * 8;
        *reinterpret_cast<uint4*>(sm + K1_P2 + pl * APLANE + r * PITCHB + c * 16) =
            *reinterpret_cast<const uint4*>(src);
    }
    __syncthreads();

    #pragma unroll
    for (int mt = 0; mt < 2; ++mt)
        #pragma unroll
        for (int nt = 0; nt < 4; ++nt)
            #pragma unroll
            for (int q = 0; q < 4; ++q) acc[mt][nt][q] = 0.0f;
    {
        const uint32_t aA = sb + K1_P0 + aoffA;
        const uint32_t aB = sb + K1_P2 + aoffB;
        #pragma unroll
        for (int ks = 0; ks < 8; ++ks) {
            const uint32_t ko = ks * 32;
            uint32_t ah[2][4], al[2][4];
            ldsm4(aA + ko, ah[0]);
            ldsm4(aA + 4352 + ko, ah[1]);
            ldsm4(aA + 17408 + ko, al[0]);
            ldsm4(aA + 17408 + 4352 + ko, al[1]);
            #pragma unroll
            for (int p = 0; p < 2; ++p) {
                uint32_t bh[4], bl[4];
                ldsm4(aB + p * 4352 + ko, bh);
                ldsm4(aB + APLANE + p * 4352 + ko, bl);
                #pragma unroll
                for (int mt = 0; mt < 2; ++mt) {
                    mma16816bf(acc[mt][2 * p], ah[mt], bh);
                    mma16816bf(acc[mt][2 * p], ah[mt], bl);
                    mma16816bf(acc[mt][2 * p], al[mt], bh);
                    mma16816bf(acc[mt][2 * p + 1], ah[mt], bh + 2);
                    mma16816bf(acc[mt][2 * p + 1], ah[mt], bl + 2);
                    mma16816bf(acc[mt][2 * p + 1], al[mt], bh + 2);
                }
            }
        }
    }
    {
        float bv[8];
        #pragma unroll
        for (int nt = 0; nt < 4; ++nt) {
            bv[nt * 2]     = b2[j0 + nt * 8 + 2 * tq];
            bv[nt * 2 + 1] = b2[j0 + nt * 8 + 2 * tq + 1];
        }
        size_t rowg0 = (size_t)n * LL + lh * 64;
        #pragma unroll
        for (int mt = 0; mt < 2; ++mt)
            #pragma unroll
            for (int nt = 0; nt < 4; ++nt) {
                int col = j0 + nt * 8 + 2 * tq;
                size_t row0 = rowg0 + l0w + mt * 16 + g;
                float v0 = fmaxf(acc[mt][nt][0] + bv[nt * 2], 0.0f);
                float v1 = fmaxf(acc[mt][nt][1] + bv[nt * 2 + 1], 0.0f);
                float v2 = fmaxf(acc[mt][nt][2] + bv[nt * 2], 0.0f);
                float v3 = fmaxf(acc[mt][nt][3] + bv[nt * 2 + 1], 0.0f);
                *reinterpret_cast<uint32_t*>(&g_h2f16[row0 * DH + col]) = pack_h2(v0, v1);
                *reinterpret_cast<uint32_t*>(&g_h2f16[(row0 + 8) * DH + col]) = pack_h2(v2, v3);
            }
    }
}

// ---------------------------------------------------------------------------
// k2: persistent, 296 CTAs (2/SM), fp16 single-pass MMA + register epilogue.
// ---------------------------------------------------------------------------
#define OFF_A0   0
#define OFF_A1   34816
#define OFF_B    69632
#define OFF_IDX  104448      // 128 ints
#define OFF_LC   104960
#define OFF_SS   104976      // 256 f
#define OFF_DD   106000      // 256 f
#define K2_SMEM  107024

#define NCTA 296
#define NTILES 8192

__device__ __forceinline__ void issue_A(uint32_t sb, int buf, int h, int tid) {
    uint32_t base = sb + (buf ? OFF_A1 : OFF_A0);
    const __half* src0 = g_W3f16 + (size_t)h * DIN * DH;
    #pragma unroll
    for (int i = tid; i < 2048; i += 256) {
        int r = i >> 4, c = i & 15;
        CP_ASYNC16(base + r * PITCHB + c * 16, src0 + r * 128 + c * 8);
    }
}

__global__ void __launch_bounds__(256, 2) k2_filter(
    const float* __restrict__ x, const float* __restrict__ mask,
    const float* __restrict__ tbias, float* __restrict__ out)
{
    char* sm = dynsm;
    const uint32_t sb = smem_u32(sm);
    int* sIdx = reinterpret_cast<int*>(sm + OFF_IDX);
    int* sLc  = reinterpret_cast<int*>(sm + OFF_LC);
    float* sS = reinterpret_cast<float*>(sm + OFF_SS);
    float* sD = reinterpret_cast<float*>(sm + OFF_DD);

    const int tid  = threadIdx.x;
    const int lane = tid & 31, wid = tid >> 5;
    const int g = lane >> 2, tq = lane & 3;
    const int mh = wid & 3, nh = wid >> 2;
    const int f0 = mh * 32, l0 = nh * 64;

    const int c  = blockIdx.x;
    const int ts = (int)(((long long)c * NTILES) / NCTA);
    const int te = (int)(((long long)(c + 1) * NTILES) / NCTA);

    const int rr = lane & 7, mm = lane >> 3;
    const uint32_t aoff = (uint32_t)((f0 + (mm & 1) * 8 + rr) * PITCHB + (mm >> 1) * 16);
    const uint32_t boff = (uint32_t)((l0 + (mm >> 1) * 8 + rr) * PITCHB + (mm & 1) * 16);
    const uint32_t aB = sb + OFF_B + boff;

    issue_A(sb, 0, ts & 127, tid);
    CP_COMMIT();

    int curn = -1, buf = 0, Lc = 0;
    float xr[4][16], vf[16];

    for (int t = ts; t < te; ++t) {
        const int n = t >> 7, h = t & 127;

        if (n != curn) {
            curn = n;
            if (wid == 0) {
                int base = 0;
                #pragma unroll
                for (int cc = 0; cc < 4; ++cc) {
                    float mv = mask[n * LL + cc * 32 + lane];
                    unsigned bal = __ballot_sync(0xffffffffu, mv != 0.0f);
                    int pos = __popc(bal & ((1u << lane) - 1u));
                    if (mv != 0.0f) sIdx[base + pos] = cc * 32 + lane;
                    base += __popc(bal);
                }
                if (lane == 0) *sLc = base;
            }
            __syncthreads();
            Lc = *sLc;
            {
                const uint4* bsrc = reinterpret_cast<const uint4*>(g_h2f16 + (size_t)n * LL * DH);
                #pragma unroll
                for (int i = tid; i < 2048; i += 256) {
                    int r = i >> 4, cc = i & 15;
                    uint4 v = make_uint4(0, 0, 0, 0);
                    if (r < Lc) v = bsrc[sIdx[r] * 16 + cc];
                    *reinterpret_cast<uint4*>(sm + OFF_B + r * PITCHB + cc * 16) = v;
                }
            }
            {
                const float* xp = x + (size_t)n * LL * DIN;
                #pragma unroll
                for (int slot = 0; slot < 16; ++slot) {
                    int nt = slot >> 1;
                    int l  = l0 + nt * 8 + 2 * tq + (slot & 1);
                    bool valid = l < Lc;
                    vf[slot] = valid ? 1.0f : 0.0f;
                    int li = valid ? sIdx[l] : 0;
                    #pragma unroll
                    for (int fr = 0; fr < 4; ++fr) {
                        int f = f0 + (fr >> 1) * 16 + (fr & 1) * 8 + g;
                        xr[fr][slot] = valid ? xp[(size_t)li * DIN + f] : 0.0f;
                    }
                }
            }
        }

        if (t + 1 < te) issue_A(sb, buf ^ 1, (t + 1) & 127, tid);
        CP_COMMIT();
        CP_WAIT1();
        __syncthreads();   // A(t) + (on n-switch) B visible

        const uint32_t aA = sb + (buf ? OFF_A1 : OFF_A0) + aoff;

        float acc[2][8][4];
        #pragma unroll
        for (int mt = 0; mt < 2; ++mt)
            #pragma unroll
            for (int nt = 0; nt < 8; ++nt)
                #pragma unroll
                for (int q = 0; q < 4; ++q) acc[mt][nt][q] = 0.0f;

        #pragma unroll
        for (int ks = 0; ks < 8; ++ks) {
            const uint32_t ko = ks * 32;
            uint32_t ah[2][4];
            ldsm4(aA + ko, ah[0]);
            ldsm4(aA + 4352 + ko, ah[1]);
            #pragma unroll
            for (int p = 0; p < 4; ++p) {
                int lp = l0 + p * 16;
                if (lp < Lc) {
                    uint32_t bh[4];
                    ldsm4(aB + p * 4352 + ko, bh);
                    mma16816h(acc[0][2 * p], ah[0], bh);
                    mma16816h(acc[1][2 * p], ah[1], bh);
                    if (lp + 8 < Lc) {
                        mma16816h(acc[0][2 * p + 1], ah[0], bh + 2);
                        mma16816h(acc[1][2 * p + 1], ah[1], bh + 2);
                    }
                }
            }
        }
        buf ^= 1;

        // register epilogue (exp on MUFU pipe, contraction on FMA pipe)
        float s[4] = {0, 0, 0, 0}, d[4] = {0, 0, 0, 0};
        #pragma unroll
        for (int mt = 0; mt < 2; ++mt)
            #pragma unroll
            for (int nt = 0; nt < 8; ++nt) {
                int s0 = nt * 2, s1 = nt * 2 + 1;
                int fr = mt * 2;
                float e0 = __expf(acc[mt][nt][0]) * vf[s0];
                float e1 = __expf(acc[mt][nt][1]) * vf[s1];
                float e2 = __expf(acc[mt][nt][2]) * vf[s0];
                float e3 = __expf(acc[mt][nt][3]) * vf[s1];
                s[fr]     += e0 + e1;
                s[fr + 1] += e2 + e3;
                d[fr]     = fmaf(xr[fr][s0], e0, d[fr]);
                d[fr]     = fmaf(xr[fr][s1], e1, d[fr]);
                d[fr + 1] = fmaf(xr[fr + 1][s0], e2, d[fr + 1]);
                d[fr + 1] = fmaf(xr[fr + 1][s1], e3, d[fr + 1]);
            }
        #pragma unroll
        for (int fr = 0; fr < 4; ++fr) {
            s[fr] += __shfl_xor_sync(0xffffffffu, s[fr], 1);
            s[fr] += __shfl_xor_sync(0xffffffffu, s[fr], 2);
            d[fr] += __shfl_xor_sync(0xffffffffu, d[fr], 1);
            d[fr] += __shfl_xor_sync(0xffffffffu, d[fr], 2);
        }
        __syncthreads();
        if (tq == 0) {
            #pragma unroll
            for (int fr = 0; fr < 4; ++fr) {
                sS[wid * 32 + fr * 8 + g] = s[fr];
                sD[wid * 32 + fr * 8 + g] = d[fr];
            }
        }
        __syncthreads();
        if (wid == 0) {
            float r = 0.0f;
            #pragma unroll
            for (int q = 0; q < 4; ++q) {
                int f = lane + q * 32;
                int i0 = (f >> 5) * 32 + ((f >> 3) & 3) * 8 + (f & 7);
                float ss = sS[i0] + sS[i0 + 128];
                float dd = sD[i0] + sD[i0 + 128];
                r += __fdividef(dd, ss);
            }
            #pragma unroll
            for (int o = 16; o; o >>= 1) r += __shfl_xor_sync(0xffffffffu, r, o);
            if (lane == 0)
                out[n * DH + h] = fmaxf(r + tbias[h], 0.0f);
        }
    }
}

// ---------------------------------------------------------------------------
extern "C" void kernel_launch(void* const* d_in, const int* in_sizes, int n_in,
                              void* d_out, int out_size) {
    const float* x    = (const float*)d_in[0];
    const float* mask = (const float*)d_in[1];
    const float* W1   = (const float*)d_in[2];
    const float* b1   = (const float*)d_in[3];
    const float* W2   = (const float*)d_in[4];
    const float* b2   = (const float*)d_in[5];
    const float* W3   = (const float*)d_in[6];
    // d_in[7] = b3: per-feature constant over l -> cancels in the softmax
    const float* tb   = (const float*)d_in[8];
    float* out = (float*)d_out;

    const int smem0 = 64 * 129 * (int)sizeof(float);
    const int smem1 = K1_SMEM;
    const int smem2 = K2_SMEM;

    cudaFuncSetAttribute(k0_trans,  cudaFuncAttributeMaxDynamicSharedMemorySize, smem0);
    cudaFuncSetAttribute(k1_mlp,    cudaFuncAttributeMaxDynamicSharedMemorySize, smem1);
    cudaFuncSetAttribute(k2_filter, cudaFuncAttributeMaxDynamicSharedMemorySize, smem2);

    k0_trans<<<dim3(130, 2), 256, smem0>>>(W3, W1, W2);
    k1_mlp<<<NB * 2, 256, smem1>>>(x, b1, b2);
    k2_filter<<<NCTA, 256, smem2>>>(x, mask, tb, out);
}

// round 12
// speedup vs baseline: 8.2800x; 1.1869x over previous
#include <cuda_runtime.h>
#include <cuda_bf16.h>
#include <cuda_fp16.h>
#include <cstdint>

#define NB   64
#define LL   128
#define DIN  128
#define DH   128
#define PITCHB 272      // b16 tile row pitch in BYTES (136 elems)

extern __shared__ char dynsm[];

__device__ __half g_W3f16[DH * DIN * DH];    // [h][f][k]
__device__ __half g_W1f16[DIN * DH];         // [j][k]
__device__ __half g_W2f16[DH * DH];          // [k'][j]
__device__ __half g_h2f16[NB * LL * DH];     // [n][l][k]

// ---------------------------------------------------------------------------
__device__ __forceinline__ uint32_t smem_u32(const void* p) {
    uint32_t a;
    asm("{ .reg .u64 t; cvta.to.shared.u64 t, %1; cvt.u32.u64 %0, t; }" : "=r"(a) : "l"(p));
    return a;
}
__device__ __forceinline__ void mma16816h(float* c, const uint32_t* a, const uint32_t* b) {
    asm volatile(
        "mma.sync.aligned.m16n8k16.row.col.f32.f16.f16.f32 "
        "{%0,%1,%2,%3}, {%4,%5,%6,%7}, {%8,%9}, {%0,%1,%2,%3};"
        : "+f"(c[0]), "+f"(c[1]), "+f"(c[2]), "+f"(c[3])
        : "r"(a[0]), "r"(a[1]), "r"(a[2]), "r"(a[3]), "r"(b[0]), "r"(b[1]));
}
__device__ __forceinline__ void ldsm4(uint32_t addr, uint32_t r[4]) {
    asm volatile("ldmatrix.sync.aligned.m8n8.x4.shared.b16 {%0,%1,%2,%3}, [%4];"
                 : "=r"(r[0]), "=r"(r[1]), "=r"(r[2]), "=r"(r[3]) : "r"(addr));
}
#define CP_ASYNC16(dst32, srcgen) \
    asm volatile("cp.async.cg.shared.global [%0], [%1], 16;" \
                 :: "r"(dst32), "l"(__cvta_generic_to_global(srcgen)) : "memory")
#define CP_COMMIT()  asm volatile("cp.async.commit_group;" ::: "memory")
#define CP_WAIT1()   asm volatile("cp.async.wait_group 1;" ::: "memory")

__device__ __forceinline__ uint32_t pack_h2(float a, float b) {
    __half2 h = __floats2half2_rn(a, b);
    return *reinterpret_cast<uint32_t*>(&h);
}

// ---------------------------------------------------------------------------
// k0: W3 -> fp16 [h][f][k] (bx<128); W1 (bx==128), W2 (bx==129) -> fp16 T
// ---------------------------------------------------------------------------
__global__ void __launch_bounds__(256) k0_trans(
    const float* __restrict__ W3, const float* __restrict__ W1, const float* __restrict__ W2)
{
    float* s = reinterpret_cast<float*>(dynsm);   // [64][129]
    int bx = blockIdx.x, zc = blockIdx.y, tid = threadIdx.x;

    const float* src;
    size_t stride;
    __half* dst;
    if (bx < 128) {
        src = W3 + (size_t)(zc * 64) * (DIN * DH) + bx * DIN;
        stride = DIN * DH;
        dst = g_W3f16 + (size_t)bx * DIN * DH;
    } else {
        src = (bx == 128 ? W1 : W2) + (size_t)(zc * 64) * DH;
        stride = DH;
        dst = (bx == 128) ? g_W1f16 : g_W2f16;
    }
    for (int i = tid; i < 8192; i += 256) {
        int kk = i >> 7, f = i & 127;
        s[kk * 129 + f] = src[(size_t)kk * stride + f];
    }
    __syncthreads();
    for (int i = tid; i < 8192; i += 256) {
        int f = i >> 6, kk = i & 63;
        dst[(size_t)f * 128 + zc * 64 + kk] = __float2half(s[kk * 129 + f]);
    }
}

// ---------------------------------------------------------------------------
// k1: fp16 single-pass 2-layer MLP. grid 128 = (n, l-half). 256 thr.
// P0 = x fp16 (64 rows); P1 = h1 fp16 (64 rows); P2 = W1t then W2t (128 rows).
// ---------------------------------------------------------------------------
#define K1_P0   0
#define K1_P1   17408
#define K1_P2   34816
#define K1_SMEM 69632     // P2 + 128*272 (R10 bug was 52224: 17KB under-allocated)

__global__ void __launch_bounds__(256, 1) k1_mlp(
    const float* __restrict__ x, const float* __restrict__ b1, const float* __restrict__ b2)
{
    char* sm = dynsm;
    const uint32_t sb = smem_u32(sm);
    const int tid = threadIdx.x;
    const int lane = tid & 31, wid = tid >> 5;
    const int g = lane >> 2, tq = lane & 3;
    const int jh = wid & 3, lw = wid >> 2;
    const int j0 = jh * 32, l0w = lw * 32;
    const int n = blockIdx.x >> 1, lh = blockIdx.x & 1;

    // x -> fp16 P0
    {
        const float* xp = x + ((size_t)n * LL + lh * 64) * DIN;
        for (int i = tid; i < 4096; i += 256) {
            int r = i >> 6, c2 = i & 63;
            float2 v = reinterpret_cast<const float2*>(xp + (size_t)r * DIN)[c2];
            *reinterpret_cast<uint32_t*>(sm + K1_P0 + r * PITCHB + c2 * 4) = pack_h2(v.x, v.y);
        }
    }
    // W1t -> P2
    for (int i = tid; i < 2048; i += 256) {
        int r = i >> 4, c = i & 15;
        *reinterpret_cast<uint4*>(sm + K1_P2 + r * PITCHB + c * 16) =
            *reinterpret_cast<const uint4*>(g_W1f16 + r * 128 + c * 8);
    }
    __syncthreads();

    const int rr = lane & 7, mm = lane >> 3;
    const uint32_t aoffA = (uint32_t)((l0w + (mm & 1) * 8 + rr) * PITCHB + (mm >> 1) * 16);
    const uint32_t aoffB = (uint32_t)((j0 + (mm >> 1) * 8 + rr) * PITCHB + (mm & 1) * 16);

    float acc[2][4][4];
    #pragma unroll
    for (int mt = 0; mt < 2; ++mt)
        #pragma unroll
        for (int nt = 0; nt < 4; ++nt)
            #pragma unroll
            for (int q = 0; q < 4; ++q) acc[mt][nt][q] = 0.0f;

    // GEMM1: h1 = relu(x @ W1 + b1)
    {
        const uint32_t aA = sb + K1_P0 + aoffA;
        const uint32_t aB = sb + K1_P2 + aoffB;
        #pragma unroll
        for (int ks = 0; ks < 8; ++ks) {
            const uint32_t ko = ks * 32;
            uint32_t a0[4], a1[4], b0[4], b1r[4];
            ldsm4(aA + ko, a0);
            ldsm4(aA + 4352 + ko, a1);
            ldsm4(aB + ko, b0);
            ldsm4(aB + 4352 + ko, b1r);
            mma16816h(acc[0][0], a0, b0); mma16816h(acc[0][1], a0, b0 + 2);
            mma16816h(acc[0][2], a0, b1r); mma16816h(acc[0][3], a0, b1r + 2);
            mma16816h(acc[1][0], a1, b0); mma16816h(acc[1][1], a1, b0 + 2);
            mma16816h(acc[1][2], a1, b1r); mma16816h(acc[1][3], a1, b1r + 2);
        }
    }
    // h1 -> P1 (disjoint from P0/P2: no WAR hazard)
    {
        float bv[8];
        #pragma unroll
        for (int nt = 0; nt < 4; ++nt) {
            bv[nt * 2]     = b1[j0 + nt * 8 + 2 * tq];
            bv[nt * 2 + 1] = b1[j0 + nt * 8 + 2 * tq + 1];
        }
        #pragma unroll
        for (int mt = 0; mt < 2; ++mt)
            #pragma unroll
            for (int nt = 0; nt < 4; ++nt) {
                int col = j0 + nt * 8 + 2 * tq;
                int row0 = l0w + mt * 16 + g;
                float v0 = fmaxf(acc[mt][nt][0] + bv[nt * 2], 0.0f);
                float v1 = fmaxf(acc[mt][nt][1] + bv[nt * 2 + 1], 0.0f);
                float v2 = fmaxf(acc[mt][nt][2] + bv[nt * 2], 0.0f);
                float v3 = fmaxf(acc[mt][nt][3] + bv[nt * 2 + 1], 0.0f);
                *reinterpret_cast<uint32_t*>(sm + K1_P1 + row0 * PITCHB + col * 2) = pack_h2(v0, v1);
                *reinterpret_cast<uint32_t*>(sm + K1_P1 + (row0 + 8) * PITCHB + col * 2) = pack_h2(v2, v3);
            }
    }
    __syncthreads();   // GEMM1 reads of P2 done; h1 visible
    // W2t -> P2
    for (int i = tid; i < 2048; i += 256) {
        int r = i >> 4, c = i & 15;
        *reinterpret_cast<uint4*>(sm + K1_P2 + r * PITCHB + c * 16) =
            *reinterpret_cast<const uint4*>(g_W2f16 + r * 128 + c * 8);
    }
    __syncthreads();

    #pragma unroll
    for (int mt = 0; mt < 2; ++mt)
        #pragma unroll
        for (int nt = 0; nt < 4; ++nt)
            #pragma unroll
            for (int q = 0; q < 4; ++q) acc[mt][nt][q] = 0.0f;

    // GEMM2: h2 = relu(h1 @ W2 + b2)
    {
        const uint32_t aA = sb + K1_P1 + aoffA;
        const uint32_t aB = sb + K1_P2 + aoffB;
        #pragma unroll
        for (int ks = 0; ks < 8; ++ks) {
            const uint32_t ko = ks * 32;
            uint32_t a0[4], a1[4], b0[4], b1r[4];
            ldsm4(aA + ko, a0);
            ldsm4(aA + 4352 + ko, a1);
            ldsm4(aB + ko, b0);
            ldsm4(aB + 4352 + ko, b1r);
            mma16816h(acc[0][0], a0, b0); mma16816h(acc[0][1], a0, b0 + 2);
            mma16816h(acc[0][2], a0, b1r); mma16816h(acc[0][3], a0, b1r + 2);
            mma16816h(acc[1][0], a1, b0); mma16816h(acc[1][1], a1, b0 + 2);
            mma16816h(acc[1][2], a1, b1r); mma16816h(acc[1][3], a1, b1r + 2);
        }
    }
    {
        float bv[8];
        #pragma unroll
        for (int nt = 0; nt < 4; ++nt) {
            bv[nt * 2]     = b2[j0 + nt * 8 + 2 * tq];
            bv[nt * 2 + 1] = b2[j0 + nt * 8 + 2 * tq + 1];
        }
        size_t rowg0 = (size_t)n * LL + lh * 64;
        #pragma unroll
        for (int mt = 0; mt < 2; ++mt)
            #pragma unroll
            for (int nt = 0; nt < 4; ++nt) {
                int col = j0 + nt * 8 + 2 * tq;
                size_t row0 = rowg0 + l0w + mt * 16 + g;
                float v0 = fmaxf(acc[mt][nt][0] + bv[nt * 2], 0.0f);
                float v1 = fmaxf(acc[mt][nt][1] + bv[nt * 2 + 1], 0.0f);
                float v2 = fmaxf(acc[mt][nt][2] + bv[nt * 2], 0.0f);
                float v3 = fmaxf(acc[mt][nt][3] + bv[nt * 2 + 1], 0.0f);
                *reinterpret_cast<uint32_t*>(&g_h2f16[row0 * DH + col]) = pack_h2(v0, v1);
                *reinterpret_cast<uint32_t*>(&g_h2f16[(row0 + 8) * DH + col]) = pack_h2(v2, v3);
            }
    }
}

// ---------------------------------------------------------------------------
// k2: persistent, 296 CTAs (2/SM), fp16 MMA + spill-free register epilogue.
// ---------------------------------------------------------------------------
#define OFF_A0   0
#define OFF_A1   34816
#define OFF_B    69632
#define OFF_IDX  104448      // 128 ints
#define OFF_LC   104960
#define OFF_SS   104976      // 256 f
#define OFF_DD   106000      // 256 f
#define K2_SMEM  107024

#define NCTA 296
#define NTILES 8192

__device__ __forceinline__ void issue_A(uint32_t sb, int buf, int h, int tid) {
    uint32_t base = sb + (buf ? OFF_A1 : OFF_A0);
    const __half* src0 = g_W3f16 + (size_t)h * DIN * DH;
    #pragma unroll
    for (int i = tid; i < 2048; i += 256) {
        int r = i >> 4, c = i & 15;
        CP_ASYNC16(base + r * PITCHB + c * 16, src0 + r * 128 + c * 8);
    }
}

__global__ void __launch_bounds__(256, 2) k2_filter(
    const float* __restrict__ x, const float* __restrict__ mask,
    const float* __restrict__ tbias, float* __restrict__ out)
{
    char* sm = dynsm;
    const uint32_t sb = smem_u32(sm);
    int* sIdx = reinterpret_cast<int*>(sm + OFF_IDX);
    int* sLc  = reinterpret_cast<int*>(sm + OFF_LC);
    float* sS = reinterpret_cast<float*>(sm + OFF_SS);
    float* sD = reinterpret_cast<float*>(sm + OFF_DD);

    const int tid  = threadIdx.x;
    const int lane = tid & 31, wid = tid >> 5;
    const int g = lane >> 2, tq = lane & 3;
    const int mh = wid & 3, nh = wid >> 2;
    const int f0 = mh * 32, l0 = nh * 64;

    const int c  = blockIdx.x;
    const int ts = (int)(((long long)c * NTILES) / NCTA);
    const int te = (int)(((long long)(c + 1) * NTILES) / NCTA);

    const int rr = lane & 7, mm = lane >> 3;
    const uint32_t aoff = (uint32_t)((f0 + (mm & 1) * 8 + rr) * PITCHB + (mm >> 1) * 16);
    const uint32_t boff = (uint32_t)((l0 + (mm >> 1) * 8 + rr) * PITCHB + (mm & 1) * 16);
    const uint32_t aB = sb + OFF_B + boff;

    issue_A(sb, 0, ts & 127, tid);
    CP_COMMIT();

    int curn = -1, buf = 0, Lc = 0;
    uint32_t xr2[4][8];        // half2 x cache: [fr][nt] = (x[l_even], x[l_odd])
    uint32_t vm = 0;           // validity bitmask over 16 slots

    for (int t = ts; t < te; ++t) {
        const int n = t >> 7, h = t & 127;

        if (n != curn) {
            curn = n;
            if (wid == 0) {
                int base = 0;
                #pragma unroll
                for (int cc = 0; cc < 4; ++cc) {
                    float mv = mask[n * LL + cc * 32 + lane];
                    unsigned bal = __ballot_sync(0xffffffffu, mv != 0.0f);
                    int pos = __popc(bal & ((1u << lane) - 1u));
                    if (mv != 0.0f) sIdx[base + pos] = cc * 32 + lane;
                    base += __popc(bal);
                }
                if (lane == 0) *sLc = base;
            }
            __syncthreads();
            Lc = *sLc;
            {
                const uint4* bsrc = reinterpret_cast<const uint4*>(g_h2f16 + (size_t)n * LL * DH);
                #pragma unroll
                for (int i = tid; i < 2048; i += 256) {
                    int r = i >> 4, cc = i & 15;
                    uint4 v = make_uint4(0, 0, 0, 0);
                    if (r < Lc) v = bsrc[sIdx[r] * 16 + cc];
                    *reinterpret_cast<uint4*>(sm + OFF_B + r * PITCHB + cc * 16) = v;
                }
            }
            {
                const float* xp = x + (size_t)n * LL * DIN;
                vm = 0;
                #pragma unroll
                for (int nt = 0; nt < 8; ++nt) {
                    int le = l0 + nt * 8 + 2 * tq;
                    int lo = le + 1;
                    bool ve = le < Lc, vo = lo < Lc;
                    if (ve) vm |= 1u << (2 * nt);
                    if (vo) vm |= 1u << (2 * nt + 1);
                    int ie = ve ? sIdx[le] : 0;
                    int io = vo ? sIdx[lo] : 0;
                    #pragma unroll
                    for (int fr = 0; fr < 4; ++fr) {
                        int f = f0 + (fr >> 1) * 16 + (fr & 1) * 8 + g;
                        float xe = ve ? xp[(size_t)ie * DIN + f] : 0.0f;
                        float xo = vo ? xp[(size_t)io * DIN + f] : 0.0f;
                        xr2[fr][nt] = pack_h2(xe, xo);
                    }
                }
            }
        }

        if (t + 1 < te) issue_A(sb, buf ^ 1, (t + 1) & 127, tid);
        CP_COMMIT();
        CP_WAIT1();
        __syncthreads();   // A(t) + (on n-switch) B visible

        const uint32_t aA = sb + (buf ? OFF_A1 : OFF_A0) + aoff;

        float acc[2][8][4];
        #pragma unroll
        for (int mt = 0; mt < 2; ++mt)
            #pragma unroll
            for (int nt = 0; nt < 8; ++nt)
                #pragma unroll
                for (int q = 0; q < 4; ++q) acc[mt][nt][q] = 0.0f;

        #pragma unroll
        for (int ks = 0; ks < 8; ++ks) {
            const uint32_t ko = ks * 32;
            uint32_t ah[2][4];
            ldsm4(aA + ko, ah[0]);
            ldsm4(aA + 4352 + ko, ah[1]);
            #pragma unroll
            for (int p = 0; p < 4; ++p) {
                int lp = l0 + p * 16;
                if (lp < Lc) {
                    uint32_t bh[4];
                    ldsm4(aB + p * 4352 + ko, bh);
                    mma16816h(acc[0][2 * p], ah[0], bh);
                    mma16816h(acc[1][2 * p], ah[1], bh);
                    if (lp + 8 < Lc) {
                        mma16816h(acc[0][2 * p + 1], ah[0], bh + 2);
                        mma16816h(acc[1][2 * p + 1], ah[1], bh + 2);
                    }
                }
            }
        }
        buf ^= 1;

        // register epilogue
        float s[4] = {0, 0, 0, 0}, d[4] = {0, 0, 0, 0};
        #pragma unroll
        for (int mt = 0; mt < 2; ++mt)
            #pragma unroll
            for (int nt = 0; nt < 8; ++nt) {
                const int s0 = 2 * nt;
                const int fr = mt * 2;
                float e0 = __expf(acc[mt][nt][0]);
                float e1 = __expf(acc[mt][nt][1]);
                float e2 = __expf(acc[mt][nt][2]);
                float e3 = __expf(acc[mt][nt][3]);
                e0 = (vm >> s0 & 1u) ? e0 : 0.0f;
                e1 = (vm >> (s0 + 1) & 1u) ? e1 : 0.0f;
                e2 = (vm >> s0 & 1u) ? e2 : 0.0f;
                e3 = (vm >> (s0 + 1) & 1u) ? e3 : 0.0f;
                float2 xlo = __half22float2(*reinterpret_cast<const __half2*>(&xr2[fr][nt]));
                float2 xhi = __half22float2(*reinterpret_cast<const __half2*>(&xr2[fr + 1][nt]));
                s[fr]     += e0 + e1;
                s[fr + 1] += e2 + e3;
                d[fr]     = fmaf(xlo.x, e0, d[fr]);
                d[fr]     = fmaf(xlo.y, e1, d[fr]);
                d[fr + 1] = fmaf(xhi.x, e2, d[fr + 1]);
                d[fr + 1] = fmaf(xhi.y, e3, d[fr + 1]);
            }
        #pragma unroll
        for (int fr = 0; fr < 4; ++fr) {
            s[fr] += __shfl_xor_sync(0xffffffffu, s[fr], 1);
            s[fr] += __shfl_xor_sync(0xffffffffu, s[fr], 2);
            d[fr] += __shfl_xor_sync(0xffffffffu, d[fr], 1);
            d[fr] += __shfl_xor_sync(0xffffffffu, d[fr], 2);
        }
        __syncthreads();
        if (tq == 0) {
            #pragma unroll
            for (int fr = 0; fr < 4; ++fr) {
                sS[wid * 32 + fr * 8 + g] = s[fr];
                sD[wid * 32 + fr * 8 + g] = d[fr];
            }
        }
        __syncthreads();
        if (wid == 0) {
            float r = 0.0f;
            #pragma unroll
            for (int q = 0; q < 4; ++q) {
                int f = lane + q * 32;
                int i0 = (f >> 5) * 32 + ((f >> 3) & 3) * 8 + (f & 7);
                float ss = sS[i0] + sS[i0 + 128];
                float dd = sD[i0] + sD[i0 + 128];
                r += __fdividef(dd, ss);
            }
            #pragma unroll
            for (int o = 16; o; o >>= 1) r += __shfl_xor_sync(0xffffffffu, r, o);
            if (lane == 0)
                out[n * DH + h] = fmaxf(r + tbias[h], 0.0f);
        }
    }
}

// ---------------------------------------------------------------------------
extern "C" void kernel_launch(void* const* d_in, const int* in_sizes, int n_in,
                              void* d_out, int out_size) {
    const float* x    = (const float*)d_in[0];
    const float* mask = (const float*)d_in[1];
    const float* W1   = (const float*)d_in[2];
    const float* b1   = (const float*)d_in[3];
    const float* W2   = (const float*)d_in[4];
    const float* b2   = (const float*)d_in[5];
    const float* W3   = (const float*)d_in[6];
    // d_in[7] = b3: per-feature constant over l -> cancels in the softmax
    const float* tb   = (const float*)d_in[8];
    float* out = (float*)d_out;

    const int smem0 = 64 * 129 * (int)sizeof(float);
    const int smem1 = K1_SMEM;
    const int smem2 = K2_SMEM;

    cudaFuncSetAttribute(k0_trans,  cudaFuncAttributeMaxDynamicSharedMemorySize, smem0);
    cudaFuncSetAttribute(k1_mlp,    cudaFuncAttributeMaxDynamicSharedMemorySize, smem1);
    cudaFuncSetAttribute(k2_filter, cudaFuncAttributeMaxDynamicSharedMemorySize, smem2);

    k0_trans<<<dim3(130, 2), 256, smem0>>>(W3, W1, W2);
    k1_mlp<<<NB * 2, 256, smem1>>>(x, b1, b2);
    k2_filter<<<NCTA, 256, smem2>>>(x, mask, tb, out);
}

// round 13
// speedup vs baseline: 8.2817x; 1.0002x over previous
#include <cuda_runtime.h>
#include <cuda_bf16.h>
#include <cuda_fp16.h>
#include <cstdint>

#define NB   64
#define LL   128
#define DIN  128
#define DH   128
#define PITCHB 272      // b16 tile row pitch in BYTES (136 elems)

extern __shared__ char dynsm[];

__device__ __half g_W3f16[DH * DIN * DH];    // [h][f][k]
__device__ __half g_W1f16[DIN * DH];         // [j][k]
__device__ __half g_W2f16[DH * DH];          // [k'][j]
__device__ __half g_h2f16[NB * LL * DH];     // [n][l][k]

// ---------------------------------------------------------------------------
__device__ __forceinline__ uint32_t smem_u32(const void* p) {
    uint32_t a;
    asm("{ .reg .u64 t; cvta.to.shared.u64 t, %1; cvt.u32.u64 %0, t; }" : "=r"(a) : "l"(p));
    return a;
}
__device__ __forceinline__ void mma16816h(float* c, const uint32_t* a, const uint32_t* b) {
    asm volatile(
        "mma.sync.aligned.m16n8k16.row.col.f32.f16.f16.f32 "
        "{%0,%1,%2,%3}, {%4,%5,%6,%7}, {%8,%9}, {%0,%1,%2,%3};"
        : "+f"(c[0]), "+f"(c[1]), "+f"(c[2]), "+f"(c[3])
        : "r"(a[0]), "r"(a[1]), "r"(a[2]), "r"(a[3]), "r"(b[0]), "r"(b[1]));
}
__device__ __forceinline__ void ldsm4(uint32_t addr, uint32_t r[4]) {
    asm volatile("ldmatrix.sync.aligned.m8n8.x4.shared.b16 {%0,%1,%2,%3}, [%4];"
                 : "=r"(r[0]), "=r"(r[1]), "=r"(r[2]), "=r"(r[3]) : "r"(addr));
}
#define CP_ASYNC16(dst32, srcgen) \
    asm volatile("cp.async.cg.shared.global [%0], [%1], 16;" \
                 :: "r"(dst32), "l"(__cvta_generic_to_global(srcgen)) : "memory")
#define CP_COMMIT()  asm volatile("cp.async.commit_group;" ::: "memory")
#define CP_WAIT1()   asm volatile("cp.async.wait_group 1;" ::: "memory")

__device__ __forceinline__ uint32_t pack_h2(float a, float b) {
    __half2 h = __floats2half2_rn(a, b);
    return *reinterpret_cast<uint32_t*>(&h);
}

// ---------------------------------------------------------------------------
// k0: W3 -> fp16 [h][f][k] (bx<128, 32-row k-chunks, zc 0..3);
//     W1 (bx==128), W2 (bx==129): 64-row chunks, zc 0..1 only.
// ---------------------------------------------------------------------------
__global__ void __launch_bounds__(256) k0_trans(
    const float* __restrict__ W3, const float* __restrict__ W1, const float* __restrict__ W2)
{
    float* s = reinterpret_cast<float*>(dynsm);   // up to [64][129]
    int bx = blockIdx.x, zc = blockIdx.y, tid = threadIdx.x;

    if (bx < 128) {
        const int kbase = zc * 32;
        const float* src = W3 + (size_t)kbase * (DIN * DH) + bx * DIN;
        for (int i = tid; i < 4096; i += 256) {
            int kk = i >> 7, f = i & 127;
            s[kk * 129 + f] = src[(size_t)kk * (DIN * DH) + f];
        }
        __syncthreads();
        __half* dst = g_W3f16 + (size_t)bx * DIN * DH;
        for (int i = tid; i < 4096; i += 256) {
            int f = i >> 5, kk = i & 31;
            dst[(size_t)f * 128 + kbase + kk] = __float2half(s[kk * 129 + f]);
        }
    } else {
        if (zc >= 2) return;
        const float* src = (bx == 128 ? W1 : W2) + (size_t)(zc * 64) * DH;
        __half* dst = (bx == 128) ? g_W1f16 : g_W2f16;
        for (int i = tid; i < 8192; i += 256) {
            int kk = i >> 7, f = i & 127;
            s[kk * 129 + f] = src[(size_t)kk * DH + f];
        }
        __syncthreads();
        for (int i = tid; i < 8192; i += 256) {
            int f = i >> 6, kk = i & 63;
            dst[(size_t)f * 128 + zc * 64 + kk] = __float2half(s[kk * 129 + f]);
        }
    }
}

// ---------------------------------------------------------------------------
// k1: fp16 single-pass 2-layer MLP. grid 128 = (n, l-half). 256 thr.
// P0 = x fp16 (64 rows); P1 = h1 fp16 (64 rows); P2 = W1t then W2t (128 rows).
// ---------------------------------------------------------------------------
#define K1_P0   0
#define K1_P1   17408
#define K1_P2   34816
#define K1_SMEM 69632

__global__ void __launch_bounds__(256, 1) k1_mlp(
    const float* __restrict__ x, const float* __restrict__ b1, const float* __restrict__ b2)
{
    char* sm = dynsm;
    const uint32_t sb = smem_u32(sm);
    const int tid = threadIdx.x;
    const int lane = tid & 31, wid = tid >> 5;
    const int g = lane >> 2, tq = lane & 3;
    const int jh = wid & 3, lw = wid >> 2;
    const int j0 = jh * 32, l0w = lw * 32;
    const int n = blockIdx.x >> 1, lh = blockIdx.x & 1;

    // x -> fp16 P0
    {
        const float* xp = x + ((size_t)n * LL + lh * 64) * DIN;
        for (int i = tid; i < 4096; i += 256) {
            int r = i >> 6, c2 = i & 63;
            float2 v = reinterpret_cast<const float2*>(xp + (size_t)r * DIN)[c2];
            *reinterpret_cast<uint32_t*>(sm + K1_P0 + r * PITCHB + c2 * 4) = pack_h2(v.x, v.y);
        }
    }
    // W1t -> P2
    for (int i = tid; i < 2048; i += 256) {
        int r = i >> 4, c = i & 15;
        *reinterpret_cast<uint4*>(sm + K1_P2 + r * PITCHB + c * 16) =
            *reinterpret_cast<const uint4*>(g_W1f16 + r * 128 + c * 8);
    }
    __syncthreads();

    const int rr = lane & 7, mm = lane >> 3;
    const uint32_t aoffA = (uint32_t)((l0w + (mm & 1) * 8 + rr) * PITCHB + (mm >> 1) * 16);
    const uint32_t aoffB = (uint32_t)((j0 + (mm >> 1) * 8 + rr) * PITCHB + (mm & 1) * 16);

    float acc[2][4][4];
    #pragma unroll
    for (int mt = 0; mt < 2; ++mt)
        #pragma unroll
        for (int nt = 0; nt < 4; ++nt)
            #pragma unroll
            for (int q = 0; q < 4; ++q) acc[mt][nt][q] = 0.0f;

    // GEMM1: h1 = relu(x @ W1 + b1)
    {
        const uint32_t aA = sb + K1_P0 + aoffA;
        const uint32_t aB = sb + K1_P2 + aoffB;
        #pragma unroll
        for (int ks = 0; ks < 8; ++ks) {
            const uint32_t ko = ks * 32;
            uint32_t a0[4], a1[4], b0[4], b1r[4];
            ldsm4(aA + ko, a0);
            ldsm4(aA + 4352 + ko, a1);
            ldsm4(aB + ko, b0);
            ldsm4(aB + 4352 + ko, b1r);
            mma16816h(acc[0][0], a0, b0); mma16816h(acc[0][1], a0, b0 + 2);
            mma16816h(acc[0][2], a0, b1r); mma16816h(acc[0][3], a0, b1r + 2);
            mma16816h(acc[1][0], a1, b0); mma16816h(acc[1][1], a1, b0 + 2);
            mma16816h(acc[1][2], a1, b1r); mma16816h(acc[1][3], a1, b1r + 2);
        }
    }
    // h1 -> P1 (disjoint from P0/P2: no WAR hazard)
    {
        float bv[8];
        #pragma unroll
        for (int nt = 0; nt < 4; ++nt) {
            bv[nt * 2]     = b1[j0 + nt * 8 + 2 * tq];
            bv[nt * 2 + 1] = b1[j0 + nt * 8 + 2 * tq + 1];
        }
        #pragma unroll
        for (int mt = 0; mt < 2; ++mt)
            #pragma unroll
            for (int nt = 0; nt < 4; ++nt) {
                int col = j0 + nt * 8 + 2 * tq;
                int row0 = l0w + mt * 16 + g;
                float v0 = fmaxf(acc[mt][nt][0] + bv[nt * 2], 0.0f);
                float v1 = fmaxf(acc[mt][nt][1] + bv[nt * 2 + 1], 0.0f);
                float v2 = fmaxf(acc[mt][nt][2] + bv[nt * 2], 0.0f);
                float v3 = fmaxf(acc[mt][nt][3] + bv[nt * 2 + 1], 0.0f);
                *reinterpret_cast<uint32_t*>(sm + K1_P1 + row0 * PITCHB + col * 2) = pack_h2(v0, v1);
                *reinterpret_cast<uint32_t*>(sm + K1_P1 + (row0 + 8) * PITCHB + col * 2) = pack_h2(v2, v3);
            }
    }
    __syncthreads();   // GEMM1 reads of P2 done; h1 visible
    // W2t -> P2
    for (int i = tid; i < 2048; i += 256) {
        int r = i >> 4, c = i & 15;
        *reinterpret_cast<uint4*>(sm + K1_P2 + r * PITCHB + c * 16) =
            *reinterpret_cast<const uint4*>(g_W2f16 + r * 128 + c * 8);
    }
    __syncthreads();

    #pragma unroll
    for (int mt = 0; mt < 2; ++mt)
        #pragma unroll
        for (int nt = 0; nt < 4; ++nt)
            #pragma unroll
            for (int q = 0; q < 4; ++q) acc[mt][nt][q] = 0.0f;

    // GEMM2: h2 = relu(h1 @ W2 + b2)
    {
        const uint32_t aA = sb + K1_P1 + aoffA;
        const uint32_t aB = sb + K1_P2 + aoffB;
        #pragma unroll
        for (int ks = 0; ks < 8; ++ks) {
            const uint32_t ko = ks * 32;
            uint32_t a0[4], a1[4], b0[4], b1r[4];
            ldsm4(aA + ko, a0);
            ldsm4(aA + 4352 + ko, a1);
            ldsm4(aB + ko, b0);
            ldsm4(aB + 4352 + ko, b1r);
            mma16816h(acc[0][0], a0, b0); mma16816h(acc[0][1], a0, b0 + 2);
            mma16816h(acc[0][2], a0, b1r); mma16816h(acc[0][3], a0, b1r + 2);
            mma16816h(acc[1][0], a1, b0); mma16816h(acc[1][1], a1, b0 + 2);
            mma16816h(acc[1][2], a1, b1r); mma16816h(acc[1][3], a1, b1r + 2);
        }
    }
    {
        float bv[8];
        #pragma unroll
        for (int nt = 0; nt < 4; ++nt) {
            bv[nt * 2]     = b2[j0 + nt * 8 + 2 * tq];
            bv[nt * 2 + 1] = b2[j0 + nt * 8 + 2 * tq + 1];
        }
        size_t rowg0 = (size_t)n * LL + lh * 64;
        #pragma unroll
        for (int mt = 0; mt < 2; ++mt)
            #pragma unroll
            for (int nt = 0; nt < 4; ++nt) {
                int col = j0 + nt * 8 + 2 * tq;
                size_t row0 = rowg0 + l0w + mt * 16 + g;
                float v0 = fmaxf(acc[mt][nt][0] + bv[nt * 2], 0.0f);
                float v1 = fmaxf(acc[mt][nt][1] + bv[nt * 2 + 1], 0.0f);
                float v2 = fmaxf(acc[mt][nt][2] + bv[nt * 2], 0.0f);
                float v3 = fmaxf(acc[mt][nt][3] + bv[nt * 2 + 1], 0.0f);
                *reinterpret_cast<uint32_t*>(&g_h2f16[row0 * DH + col]) = pack_h2(v0, v1);
                *reinterpret_cast<uint32_t*>(&g_h2f16[(row0 + 8) * DH + col]) = pack_h2(v2, v3);
            }
    }
}

// ---------------------------------------------------------------------------
// k2: persistent, 296 CTAs (2/SM), fp16 MMA + trimmed register epilogue.
// ---------------------------------------------------------------------------
#define OFF_A0   0
#define OFF_A1   34816
#define OFF_B    69632
#define OFF_IDX  104448      // 128 ints
#define OFF_LC   104960
#define OFF_SS   104976      // 256 f
#define OFF_DD   106000      // 256 f
#define K2_SMEM  107024

#define NCTA 296
#define NTILES 8192

__device__ __forceinline__ void issue_A(uint32_t sb, int buf, int h, int tid) {
    uint32_t base = sb + (buf ? OFF_A1 : OFF_A0);
    const __half* src0 = g_W3f16 + (size_t)h * DIN * DH;
    #pragma unroll
    for (int i = tid; i < 2048; i += 256) {
        int r = i >> 4, c = i & 15;
        CP_ASYNC16(base + r * PITCHB + c * 16, src0 + r * 128 + c * 8);
    }
}

__global__ void __launch_bounds__(256, 2) k2_filter(
    const float* __restrict__ x, const float* __restrict__ mask,
    const float* __restrict__ tbias, float* __restrict__ out)
{
    char* sm = dynsm;
    const uint32_t sb = smem_u32(sm);
    int* sIdx = reinterpret_cast<int*>(sm + OFF_IDX);
    int* sLc  = reinterpret_cast<int*>(sm + OFF_LC);
    float* sS = reinterpret_cast<float*>(sm + OFF_SS);
    float* sD = reinterpret_cast<float*>(sm + OFF_DD);

    const int tid  = threadIdx.x;
    const int lane = tid & 31, wid = tid >> 5;
    const int g = lane >> 2, tq = lane & 3;
    const int mh = wid & 3, nh = wid >> 2;
    const int f0 = mh * 32, l0 = nh * 64;

    const int c  = blockIdx.x;
    const int ts = (int)(((long long)c * NTILES) / NCTA);
    const int te = (int)(((long long)(c + 1) * NTILES) / NCTA);

    const int rr = lane & 7, mm = lane >> 3;
    const uint32_t aoff = (uint32_t)((f0 + (mm & 1) * 8 + rr) * PITCHB + (mm >> 1) * 16);
    const uint32_t boff = (uint32_t)((l0 + (mm >> 1) * 8 + rr) * PITCHB + (mm & 1) * 16);
    const uint32_t aB = sb + OFF_B + boff;

    issue_A(sb, 0, ts & 127, tid);
    CP_COMMIT();

    int curn = -1, buf = 0, Lc = 0;
    uint32_t xr2[4][8];        // half2 x cache: [fr][nt] = (x[l_even], x[l_odd])
    uint32_t vm = 0;           // validity bitmask over 16 slots
    float invF = 0.0f;         // count of invalid slots inside executed nt-groups

    for (int t = ts; t < te; ++t) {
        const int n = t >> 7, h = t & 127;

        if (n != curn) {
            curn = n;
            if (wid == 0) {
                int base = 0;
                #pragma unroll
                for (int cc = 0; cc < 4; ++cc) {
                    float mv = mask[n * LL + cc * 32 + lane];
                    unsigned bal = __ballot_sync(0xffffffffu, mv != 0.0f);
                    int pos = __popc(bal & ((1u << lane) - 1u));
                    if (mv != 0.0f) sIdx[base + pos] = cc * 32 + lane;
                    base += __popc(bal);
                }
                if (lane == 0) *sLc = base;
            }
            __syncthreads();
            Lc = *sLc;
            {
                const uint4* bsrc = reinterpret_cast<const uint4*>(g_h2f16 + (size_t)n * LL * DH);
                #pragma unroll
                for (int i = tid; i < 2048; i += 256) {
                    int r = i >> 4, cc = i & 15;
                    uint4 v = make_uint4(0, 0, 0, 0);
                    if (r < Lc) v = bsrc[sIdx[r] * 16 + cc];
                    *reinterpret_cast<uint4*>(sm + OFF_B + r * PITCHB + cc * 16) = v;
                }
            }
            {
                const float* xp = x + (size_t)n * LL * DIN;
                vm = 0;
                #pragma unroll
                for (int nt = 0; nt < 8; ++nt) {
                    int le = l0 + nt * 8 + 2 * tq;
                    int lo = le + 1;
                    bool ve = le < Lc, vo = lo < Lc;
                    if (ve) vm |= 1u << (2 * nt);
                    if (vo) vm |= 1u << (2 * nt + 1);
                    int ie = ve ? sIdx[le] : 0;
                    int io = vo ? sIdx[lo] : 0;
                    #pragma unroll
                    for (int fr = 0; fr < 4; ++fr) {
                        int f = f0 + (fr >> 1) * 16 + (fr & 1) * 8 + g;
                        float xe = ve ? xp[(size_t)ie * DIN + f] : 0.0f;
                        float xo = vo ? xp[(size_t)io * DIN + f] : 0.0f;
                        xr2[fr][nt] = pack_h2(xe, xo);
                    }
                }
                // invalid slots within executed (any-valid) nt groups: their acc
                // stays exactly 0 -> exp = 1 -> subtract the count from s.
                uint32_t anyg = (vm | (vm >> 1)) & 0x5555u;
                uint32_t execMask = anyg | (anyg << 1);
                invF = (float)__popc(execMask & ~vm & 0xFFFFu);
            }
        }

        if (t + 1 < te) issue_A(sb, buf ^ 1, (t + 1) & 127, tid);
        CP_COMMIT();
        CP_WAIT1();
        __syncthreads();   // A(t) + (on n-switch) B visible

        const uint32_t aA = sb + (buf ? OFF_A1 : OFF_A0) + aoff;

        float acc[2][8][4];
        #pragma unroll
        for (int mt = 0; mt < 2; ++mt)
            #pragma unroll
            for (int nt = 0; nt < 8; ++nt)
                #pragma unroll
                for (int q = 0; q < 4; ++q) acc[mt][nt][q] = 0.0f;

        #pragma unroll
        for (int ks = 0; ks < 8; ++ks) {
            const uint32_t ko = ks * 32;
            uint32_t ah[2][4];
            ldsm4(aA + ko, ah[0]);
            ldsm4(aA + 4352 + ko, ah[1]);
            #pragma unroll
            for (int p = 0; p < 4; ++p) {
                int lp = l0 + p * 16;
                if (lp < Lc) {
                    uint32_t bh[4];
                    ldsm4(aB + p * 4352 + ko, bh);
                    mma16816h(acc[0][2 * p], ah[0], bh);
                    mma16816h(acc[1][2 * p], ah[1], bh);
                    if (lp + 8 < Lc) {
                        mma16816h(acc[0][2 * p + 1], ah[0], bh + 2);
                        mma16816h(acc[1][2 * p + 1], ah[1], bh + 2);
                    }
                }
            }
        }
        buf ^= 1;

        // register epilogue: skip all-invalid nt groups (warp-uniform),
        // no per-element masking (x already zeroed; s fixed via invF).
        float s[4] = {0, 0, 0, 0}, d[4] = {0, 0, 0, 0};
        #pragma unroll
        for (int nt = 0; nt < 8; ++nt) {
            if (((vm >> (2 * nt)) & 3u) != 0u) {
                float e00 = __expf(acc[0][nt][0]);
                float e01 = __expf(acc[0][nt][1]);
                float e02 = __expf(acc[0][nt][2]);
                float e03 = __expf(acc[0][nt][3]);
                float e10 = __expf(acc[1][nt][0]);
                float e11 = __expf(acc[1][nt][1]);
                float e12 = __expf(acc[1][nt][2]);
                float e13 = __expf(acc[1][nt][3]);
                float2 x0 = __half22float2(*reinterpret_cast<const __half2*>(&xr2[0][nt]));
                float2 x1 = __half22float2(*reinterpret_cast<const __half2*>(&xr2[1][nt]));
                float2 x2 = __half22float2(*reinterpret_cast<const __half2*>(&xr2[2][nt]));
                float2 x3 = __half22float2(*reinterpret_cast<const __half2*>(&xr2[3][nt]));
                s[0] += e00 + e01;
                s[1] += e02 + e03;
                s[2] += e10 + e11;
                s[3] += e12 + e13;
                d[0] = fmaf(x0.x, e00, d[0]); d[0] = fmaf(x0.y, e01, d[0]);
                d[1] = fmaf(x1.x, e02, d[1]); d[1] = fmaf(x1.y, e03, d[1]);
                d[2] = fmaf(x2.x, e10, d[2]); d[2] = fmaf(x2.y, e11, d[2]);
                d[3] = fmaf(x3.x, e12, d[3]); d[3] = fmaf(x3.y, e13, d[3]);
            }
        }
        #pragma unroll
        for (int fr = 0; fr < 4; ++fr) s[fr] -= invF;

        #pragma unroll
        for (int fr = 0; fr < 4; ++fr) {
            s[fr] += __shfl_xor_sync(0xffffffffu, s[fr], 1);
            s[fr] += __shfl_xor_sync(0xffffffffu, s[fr], 2);
            d[fr] += __shfl_xor_sync(0xffffffffu, d[fr], 1);
            d[fr] += __shfl_xor_sync(0xffffffffu, d[fr], 2);
        }
        __syncthreads();
        if (tq == 0) {
            #pragma unroll
            for (int fr = 0; fr < 4; ++fr) {
                sS[wid * 32 + fr * 8 + g] = s[fr];
                sD[wid * 32 + fr * 8 + g] = d[fr];
            }
        }
        __syncthreads();
        if (wid == 0) {
            float r = 0.0f;
            #pragma unroll
            for (int q = 0; q < 4; ++q) {
                int f = lane + q * 32;
                int i0 = (f >> 5) * 32 + ((f >> 3) & 3) * 8 + (f & 7);
                float ss = sS[i0] + sS[i0 + 128];
                float dd = sD[i0] + sD[i0 + 128];
                r += __fdividef(dd, ss);
            }
            #pragma unroll
            for (int o = 16; o; o >>= 1) r += __shfl_xor_sync(0xffffffffu, r, o);
            if (lane == 0)
                out[n * DH + h] = fmaxf(r + tbias[h], 0.0f);
        }
    }
}

// ---------------------------------------------------------------------------
extern "C" void kernel_launch(void* const* d_in, const int* in_sizes, int n_in,
                              void* d_out, int out_size) {
    const float* x    = (const float*)d_in[0];
    const float* mask = (const float*)d_in[1];
    const float* W1   = (const float*)d_in[2];
    const float* b1   = (const float*)d_in[3];
    const float* W2   = (const float*)d_in[4];
    const float* b2   = (const float*)d_in[5];
    const float* W3   = (const float*)d_in[6];
    // d_in[7] = b3: per-feature constant over l -> cancels in the softmax
    const float* tb   = (const float*)d_in[8];
    float* out = (float*)d_out;

    const int smem0 = 64 * 129 * (int)sizeof(float);
    const int smem1 = K1_SMEM;
    const int smem2 = K2_SMEM;

    cudaFuncSetAttribute(k0_trans,  cudaFuncAttributeMaxDynamicSharedMemorySize, smem0);
    cudaFuncSetAttribute(k1_mlp,    cudaFuncAttributeMaxDynamicSharedMemorySize, smem1);
    cudaFuncSetAttribute(k2_filter, cudaFuncAttributeMaxDynamicSharedMemorySize, smem2);

    k0_trans<<<dim3(130, 4), 256, smem0>>>(W3, W1, W2);
    k1_mlp<<<NB * 2, 256, smem1>>>(x, b1, b2);
    k2_filter<<<NCTA, 256, smem2>>>(x, mask, tb, out);
}

// round 14
// speedup vs baseline: 8.7503x; 1.0566x over previous
#include <cuda_runtime.h>
#include <cuda_bf16.h>
#include <cuda_fp16.h>
#include <cstdint>

#define NB   64
#define LL   128
#define DIN  128
#define DH   128
#define PITCHB 272      // b16 tile row pitch in BYTES (136 elems)
#define LOG2E 1.4426950408889634f

extern __shared__ char dynsm[];

__device__ __half g_W3f16[DH * DIN * DH];    // [h][f][k], pre-scaled by log2(e)
__device__ __half g_h2f16[NB * LL * DH];     // [n][l][k]

// ---------------------------------------------------------------------------
__device__ __forceinline__ uint32_t smem_u32(const void* p) {
    uint32_t a;
    asm("{ .reg .u64 t; cvta.to.shared.u64 t, %1; cvt.u32.u64 %0, t; }" : "=r"(a) : "l"(p));
    return a;
}
__device__ __forceinline__ float fex2(float a) {
    float r;
    asm("ex2.approx.ftz.f32 %0, %1;" : "=f"(r) : "f"(a));
    return r;
}
__device__ __forceinline__ void mma16816h(float* c, const uint32_t* a, const uint32_t* b) {
    asm volatile(
        "mma.sync.aligned.m16n8k16.row.col.f32.f16.f16.f32 "
        "{%0,%1,%2,%3}, {%4,%5,%6,%7}, {%8,%9}, {%0,%1,%2,%3};"
        : "+f"(c[0]), "+f"(c[1]), "+f"(c[2]), "+f"(c[3])
        : "r"(a[0]), "r"(a[1]), "r"(a[2]), "r"(a[3]), "r"(b[0]), "r"(b[1]));
}
__device__ __forceinline__ void ldsm4(uint32_t addr, uint32_t r[4]) {
    asm volatile("ldmatrix.sync.aligned.m8n8.x4.shared.b16 {%0,%1,%2,%3}, [%4];"
                 : "=r"(r[0]), "=r"(r[1]), "=r"(r[2]), "=r"(r[3]) : "r"(addr));
}
#define CP_ASYNC16(dst32, srcgen) \
    asm volatile("cp.async.cg.shared.global [%0], [%1], 16;" \
                 :: "r"(dst32), "l"(__cvta_generic_to_global(srcgen)) : "memory")
#define CP_COMMIT()  asm volatile("cp.async.commit_group;" ::: "memory")
#define CP_WAIT1()   asm volatile("cp.async.wait_group 1;" ::: "memory")

__device__ __forceinline__ uint32_t pack_h2(float a, float b) {
    __half2 h = __floats2half2_rn(a, b);
    return *reinterpret_cast<uint32_t*>(&h);
}

// ---------------------------------------------------------------------------
// k01: merged preprocessing.
//   bx <  128 : MLP CTA (n = bx>>1, lh = bx&1). Self-transposes W1/W2.
//   bx >= 128 : W3 convert CTA: h = (bx-128)>>2, zc = (bx-128)&3 (32 k-rows).
//               W3 is pre-scaled by LOG2E so k2's exp is a bare ex2.
// SMEM: P0 x/h-tiles 0..17407; P1 17408..34815; P2 34816..69631; STG 69632..102655
// ---------------------------------------------------------------------------
#define K1_P0   0
#define K1_P1   17408
#define K1_P2   34816
#define STG_OFF 69632
#define K01_SMEM 102656

__global__ void __launch_bounds__(256, 1) k01(
    const float* __restrict__ W3, const float* __restrict__ W1, const float* __restrict__ W2,
    const float* __restrict__ x,  const float* __restrict__ b1, const float* __restrict__ b2)
{
    char* sm = dynsm;
    const int bx = blockIdx.x, tid = threadIdx.x;

    if (bx >= 128) {
        // ---- W3 convert path ----
        float* s = reinterpret_cast<float*>(sm);   // [32][129]
        int h = (bx - 128) >> 2, zc = (bx - 128) & 3;
        const int kbase = zc * 32;
        const float* src = W3 + (size_t)kbase * (DIN * DH) + h * DIN;
        for (int i = tid; i < 4096; i += 256) {
            int kk = i >> 7, f = i & 127;
            s[kk * 129 + f] = src[(size_t)kk * (DIN * DH) + f];
        }
        __syncthreads();
        __half* dst = g_W3f16 + (size_t)h * DIN * DH;
        for (int i = tid; i < 4096; i += 256) {
            int f = i >> 5, kk = i & 31;
            dst[(size_t)f * 128 + kbase + kk] = __float2half(s[kk * 129 + f] * LOG2E);
        }
        return;
    }

    // ---- MLP path ----
    const uint32_t sb = smem_u32(sm);
    const int lane = tid & 31, wid = tid >> 5;
    const int g = lane >> 2, tq = lane & 3;
    const int jh = wid & 3, lw = wid >> 2;
    const int j0 = jh * 32, l0w = lw * 32;
    const int n = bx >> 1, lh = bx & 1;
    float* stg = reinterpret_cast<float*>(sm + STG_OFF);

    // W1 -> P2 fp16 [j][k] (2 chunks of 64 k-rows via STG)
    #pragma unroll
    for (int cch = 0; cch < 2; ++cch) {
        for (int i = tid; i < 8192; i += 256) {
            int kk = i >> 7, j = i & 127;
            stg[kk * 129 + j] = W1[(size_t)(cch * 64 + kk) * DH + j];
        }
        __syncthreads();
        for (int i = tid; i < 8192; i += 256) {
            int j = i >> 6, kk = i & 63;
            *reinterpret_cast<__half*>(sm + K1_P2 + j * PITCHB + (cch * 64 + kk) * 2) =
                __float2half(stg[kk * 129 + j]);
        }
        __syncthreads();
    }
    // x -> fp16 P0
    {
        const float* xp = x + ((size_t)n * LL + lh * 64) * DIN;
        for (int i = tid; i < 4096; i += 256) {
            int r = i >> 6, c2 = i & 63;
            float2 v = reinterpret_cast<const float2*>(xp + (size_t)r * DIN)[c2];
            *reinterpret_cast<uint32_t*>(sm + K1_P0 + r * PITCHB + c2 * 4) = pack_h2(v.x, v.y);
        }
    }
    __syncthreads();

    const int rr = lane & 7, mm = lane >> 3;
    const uint32_t aoffA = (uint32_t)((l0w + (mm & 1) * 8 + rr) * PITCHB + (mm >> 1) * 16);
    const uint32_t aoffB = (uint32_t)((j0 + (mm >> 1) * 8 + rr) * PITCHB + (mm & 1) * 16);

    float acc[2][4][4];
    #pragma unroll
    for (int mt = 0; mt < 2; ++mt)
        #pragma unroll
        for (int nt = 0; nt < 4; ++nt)
            #pragma unroll
            for (int q = 0; q < 4; ++q) acc[mt][nt][q] = 0.0f;

    // GEMM1: h1 = relu(x @ W1 + b1)
    {
        const uint32_t aA = sb + K1_P0 + aoffA;
        const uint32_t aB = sb + K1_P2 + aoffB;
        #pragma unroll
        for (int ks = 0; ks < 8; ++ks) {
            const uint32_t ko = ks * 32;
            uint32_t a0[4], a1[4], b0[4], b1r[4];
            ldsm4(aA + ko, a0);
            ldsm4(aA + 4352 + ko, a1);
            ldsm4(aB + ko, b0);
            ldsm4(aB + 4352 + ko, b1r);
            mma16816h(acc[0][0], a0, b0); mma16816h(acc[0][1], a0, b0 + 2);
            mma16816h(acc[0][2], a0, b1r); mma16816h(acc[0][3], a0, b1r + 2);
            mma16816h(acc[1][0], a1, b0); mma16816h(acc[1][1], a1, b0 + 2);
            mma16816h(acc[1][2], a1, b1r); mma16816h(acc[1][3], a1, b1r + 2);
        }
    }
    // h1 -> P1
    {
        float bv[8];
        #pragma unroll
        for (int nt = 0; nt < 4; ++nt) {
            bv[nt * 2]     = b1[j0 + nt * 8 + 2 * tq];
            bv[nt * 2 + 1] = b1[j0 + nt * 8 + 2 * tq + 1];
        }
        #pragma unroll
        for (int mt = 0; mt < 2; ++mt)
            #pragma unroll
            for (int nt = 0; nt < 4; ++nt) {
                int col = j0 + nt * 8 + 2 * tq;
                int row0 = l0w + mt * 16 + g;
                float v0 = fmaxf(acc[mt][nt][0] + bv[nt * 2], 0.0f);
                float v1 = fmaxf(acc[mt][nt][1] + bv[nt * 2 + 1], 0.0f);
                float v2 = fmaxf(acc[mt][nt][2] + bv[nt * 2], 0.0f);
                float v3 = fmaxf(acc[mt][nt][3] + bv[nt * 2 + 1], 0.0f);
                *reinterpret_cast<uint32_t*>(sm + K1_P1 + row0 * PITCHB + col * 2) = pack_h2(v0, v1);
                *reinterpret_cast<uint32_t*>(sm + K1_P1 + (row0 + 8) * PITCHB + col * 2) = pack_h2(v2, v3);
            }
    }
    __syncthreads();   // all GEMM1 reads of P2 done; h1 visible

    // W2 -> P2 fp16 [kprime][j... ] same transposed layout (2 chunks)
    #pragma unroll
    for (int cch = 0; cch < 2; ++cch) {
        for (int i = tid; i < 8192; i += 256) {
            int kk = i >> 7, j = i & 127;
            stg[kk * 129 + j] = W2[(size_t)(cch * 64 + kk) * DH + j];
        }
        __syncthreads();
        for (int i = tid; i < 8192; i += 256) {
            int j = i >> 6, kk = i & 63;
            *reinterpret_cast<__half*>(sm + K1_P2 + j * PITCHB + (cch * 64 + kk) * 2) =
                __float2half(stg[kk * 129 + j]);
        }
        __syncthreads();
    }

    #pragma unroll
    for (int mt = 0; mt < 2; ++mt)
        #pragma unroll
        for (int nt = 0; nt < 4; ++nt)
            #pragma unroll
            for (int q = 0; q < 4; ++q) acc[mt][nt][q] = 0.0f;

    // GEMM2: h2 = relu(h1 @ W2 + b2)
    {
        const uint32_t aA = sb + K1_P1 + aoffA;
        const uint32_t aB = sb + K1_P2 + aoffB;
        #pragma unroll
        for (int ks = 0; ks < 8; ++ks) {
            const uint32_t ko = ks * 32;
            uint32_t a0[4], a1[4], b0[4], b1r[4];
            ldsm4(aA + ko, a0);
            ldsm4(aA + 4352 + ko, a1);
            ldsm4(aB + ko, b0);
            ldsm4(aB + 4352 + ko, b1r);
            mma16816h(acc[0][0], a0, b0); mma16816h(acc[0][1], a0, b0 + 2);
            mma16816h(acc[0][2], a0, b1r); mma16816h(acc[0][3], a0, b1r + 2);
            mma16816h(acc[1][0], a1, b0); mma16816h(acc[1][1], a1, b0 + 2);
            mma16816h(acc[1][2], a1, b1r); mma16816h(acc[1][3], a1, b1r + 2);
        }
    }
    {
        float bv[8];
        #pragma unroll
        for (int nt = 0; nt < 4; ++nt) {
            bv[nt * 2]     = b2[j0 + nt * 8 + 2 * tq];
            bv[nt * 2 + 1] = b2[j0 + nt * 8 + 2 * tq + 1];
        }
        size_t rowg0 = (size_t)n * LL + lh * 64;
        #pragma unroll
        for (int mt = 0; mt < 2; ++mt)
            #pragma unroll
            for (int nt = 0; nt < 4; ++nt) {
                int col = j0 + nt * 8 + 2 * tq;
                size_t row0 = rowg0 + l0w + mt * 16 + g;
                float v0 = fmaxf(acc[mt][nt][0] + bv[nt * 2], 0.0f);
                float v1 = fmaxf(acc[mt][nt][1] + bv[nt * 2 + 1], 0.0f);
                float v2 = fmaxf(acc[mt][nt][2] + bv[nt * 2], 0.0f);
                float v3 = fmaxf(acc[mt][nt][3] + bv[nt * 2 + 1], 0.0f);
                *reinterpret_cast<uint32_t*>(&g_h2f16[row0 * DH + col]) = pack_h2(v0, v1);
                *reinterpret_cast<uint32_t*>(&g_h2f16[(row0 + 8) * DH + col]) = pack_h2(v2, v3);
            }
    }
}

// ---------------------------------------------------------------------------
// k2: persistent, 296 CTAs (2/SM), fp16 MMA + ex2 epilogue + banked reduction.
// ---------------------------------------------------------------------------
#define OFF_A0   0
#define OFF_A1   34816
#define OFF_B    69632
#define OFF_IDX  104448      // 128 ints
#define OFF_LC   104960
#define OFF_SS   104976      // 2 banks x 256 f
#define OFF_DD   107024      // 2 banks x 256 f
#define K2_SMEM  109072

#define NCTA 296
#define NTILES 8192

__device__ __forceinline__ void issue_A(uint32_t sb, int buf, int h, int tid) {
    uint32_t base = sb + (buf ? OFF_A1 : OFF_A0);
    const __half* src0 = g_W3f16 + (size_t)h * DIN * DH;
    #pragma unroll
    for (int i = tid; i < 2048; i += 256) {
        int r = i >> 4, c = i & 15;
        CP_ASYNC16(base + r * PITCHB + c * 16, src0 + r * 128 + c * 8);
    }
}

__global__ void __launch_bounds__(256, 2) k2_filter(
    const float* __restrict__ x, const float* __restrict__ mask,
    const float* __restrict__ tbias, float* __restrict__ out)
{
    char* sm = dynsm;
    const uint32_t sb = smem_u32(sm);
    int* sIdx = reinterpret_cast<int*>(sm + OFF_IDX);
    int* sLc  = reinterpret_cast<int*>(sm + OFF_LC);
    float* sS = reinterpret_cast<float*>(sm + OFF_SS);
    float* sD = reinterpret_cast<float*>(sm + OFF_DD);

    const int tid  = threadIdx.x;
    const int lane = tid & 31, wid = tid >> 5;
    const int g = lane >> 2, tq = lane & 3;
    const int mh = wid & 3, nh = wid >> 2;
    const int f0 = mh * 32, l0 = nh * 64;

    const int c  = blockIdx.x;
    const int ts = (int)(((long long)c * NTILES) / NCTA);
    const int te = (int)(((long long)(c + 1) * NTILES) / NCTA);

    const int rr = lane & 7, mm = lane >> 3;
    const uint32_t aoff = (uint32_t)((f0 + (mm & 1) * 8 + rr) * PITCHB + (mm >> 1) * 16);
    const uint32_t boff = (uint32_t)((l0 + (mm >> 1) * 8 + rr) * PITCHB + (mm & 1) * 16);
    const uint32_t aB = sb + OFF_B + boff;

    issue_A(sb, 0, ts & 127, tid);
    CP_COMMIT();

    int curn = -1, buf = 0, Lc = 0;
    uint32_t xr2[4][8];        // half2 x cache
    uint32_t vm = 0;           // validity bitmask over 16 slots
    float invF = 0.0f;

    for (int t = ts; t < te; ++t) {
        const int n = t >> 7, h = t & 127;
        const int bank = (t & 1) << 8;   // 0 or 256

        if (n != curn) {
            curn = n;
            if (wid == 0) {
                int base = 0;
                #pragma unroll
                for (int cc = 0; cc < 4; ++cc) {
                    float mv = mask[n * LL + cc * 32 + lane];
                    unsigned bal = __ballot_sync(0xffffffffu, mv != 0.0f);
                    int pos = __popc(bal & ((1u << lane) - 1u));
                    if (mv != 0.0f) sIdx[base + pos] = cc * 32 + lane;
                    base += __popc(bal);
                }
                if (lane == 0) *sLc = base;
            }
            __syncthreads();
            Lc = *sLc;
            {
                const uint4* bsrc = reinterpret_cast<const uint4*>(g_h2f16 + (size_t)n * LL * DH);
                #pragma unroll
                for (int i = tid; i < 2048; i += 256) {
                    int r = i >> 4, cc = i & 15;
                    uint4 v = make_uint4(0, 0, 0, 0);
                    if (r < Lc) v = bsrc[sIdx[r] * 16 + cc];
                    *reinterpret_cast<uint4*>(sm + OFF_B + r * PITCHB + cc * 16) = v;
                }
            }
            {
                const float* xp = x + (size_t)n * LL * DIN;
                vm = 0;
                #pragma unroll
                for (int nt = 0; nt < 8; ++nt) {
                    int le = l0 + nt * 8 + 2 * tq;
                    int lo = le + 1;
                    bool ve = le < Lc, vo = lo < Lc;
                    if (ve) vm |= 1u << (2 * nt);
                    if (vo) vm |= 1u << (2 * nt + 1);
                    int ie = ve ? sIdx[le] : 0;
                    int io = vo ? sIdx[lo] : 0;
                    #pragma unroll
                    for (int fr = 0; fr < 4; ++fr) {
                        int f = f0 + (fr >> 1) * 16 + (fr & 1) * 8 + g;
                        float xe = ve ? xp[(size_t)ie * DIN + f] : 0.0f;
                        float xo = vo ? xp[(size_t)io * DIN + f] : 0.0f;
                        xr2[fr][nt] = pack_h2(xe, xo);
                    }
                }
                uint32_t anyg = (vm | (vm >> 1)) & 0x5555u;
                uint32_t execMask = anyg | (anyg << 1);
                invF = (float)__popc(execMask & ~vm & 0xFFFFu);
            }
        }

        if (t + 1 < te) issue_A(sb, buf ^ 1, (t + 1) & 127, tid);
        CP_COMMIT();
        CP_WAIT1();
        __syncthreads();   // A(t) + (on n-switch) B visible

        const uint32_t aA = sb + (buf ? OFF_A1 : OFF_A0) + aoff;

        float acc[2][8][4];
        #pragma unroll
        for (int mt = 0; mt < 2; ++mt)
            #pragma unroll
            for (int nt = 0; nt < 8; ++nt)
                #pragma unroll
                for (int q = 0; q < 4; ++q) acc[mt][nt][q] = 0.0f;

        #pragma unroll
        for (int ks = 0; ks < 8; ++ks) {
            const uint32_t ko = ks * 32;
            uint32_t ah[2][4];
            ldsm4(aA + ko, ah[0]);
            ldsm4(aA + 4352 + ko, ah[1]);
            #pragma unroll
            for (int p = 0; p < 4; ++p) {
                int lp = l0 + p * 16;
                if (lp < Lc) {
                    uint32_t bh[4];
                    ldsm4(aB + p * 4352 + ko, bh);
                    mma16816h(acc[0][2 * p], ah[0], bh);
                    mma16816h(acc[1][2 * p], ah[1], bh);
                    if (lp + 8 < Lc) {
                        mma16816h(acc[0][2 * p + 1], ah[0], bh + 2);
                        mma16816h(acc[1][2 * p + 1], ah[1], bh + 2);
                    }
                }
            }
        }
        buf ^= 1;

        // epilogue: logits pre-scaled by log2e -> bare ex2. Skip all-invalid groups.
        float s[4] = {0, 0, 0, 0}, d[4] = {0, 0, 0, 0};
        #pragma unroll
        for (int nt = 0; nt < 8; ++nt) {
            if (((vm >> (2 * nt)) & 3u) != 0u) {
                float e00 = fex2(acc[0][nt][0]);
                float e01 = fex2(acc[0][nt][1]);
                float e02 = fex2(acc[0][nt][2]);
                float e03 = fex2(acc[0][nt][3]);
                float e10 = fex2(acc[1][nt][0]);
                float e11 = fex2(acc[1][nt][1]);
                float e12 = fex2(acc[1][nt][2]);
                float e13 = fex2(acc[1][nt][3]);
                float2 x0 = __half22float2(*reinterpret_cast<const __half2*>(&xr2[0][nt]));
                float2 x1 = __half22float2(*reinterpret_cast<const __half2*>(&xr2[1][nt]));
                float2 x2 = __half22float2(*reinterpret_cast<const __half2*>(&xr2[2][nt]));
                float2 x3 = __half22float2(*reinterpret_cast<const __half2*>(&xr2[3][nt]));
                s[0] += e00 + e01;
                s[1] += e02 + e03;
                s[2] += e10 + e11;
                s[3] += e12 + e13;
                d[0] = fmaf(x0.x, e00, d[0]); d[0] = fmaf(x0.y, e01, d[0]);
                d[1] = fmaf(x1.x, e02, d[1]); d[1] = fmaf(x1.y, e03, d[1]);
                d[2] = fmaf(x2.x, e10, d[2]); d[2] = fmaf(x2.y, e11, d[2]);
                d[3] = fmaf(x3.x, e12, d[3]); d[3] = fmaf(x3.y, e13, d[3]);
            }
        }
        #pragma unroll
        for (int fr = 0; fr < 4; ++fr) s[fr] -= invF;

        #pragma unroll
        for (int fr = 0; fr < 4; ++fr) {
            s[fr] += __shfl_xor_sync(0xffffffffu, s[fr], 1);
            s[fr] += __shfl_xor_sync(0xffffffffu, s[fr], 2);
            d[fr] += __shfl_xor_sync(0xffffffffu, d[fr], 1);
            d[fr] += __shfl_xor_sync(0xffffffffu, d[fr], 2);
        }
        // banked sS/sD: previous tile used the other bank -> no WAR sync needed
        if (tq == 0) {
            #pragma unroll
            for (int fr = 0; fr < 4; ++fr) {
                sS[bank + wid * 32 + fr * 8 + g] = s[fr];
                sD[bank + wid * 32 + fr * 8 + g] = d[fr];
            }
        }
        __syncthreads();
        if (wid == 0) {
            float r = 0.0f;
            #pragma unroll
            for (int q = 0; q < 4; ++q) {
                int f = lane + q * 32;
                int i0 = (f >> 5) * 32 + ((f >> 3) & 3) * 8 + (f & 7);
                float ss = sS[bank + i0] + sS[bank + i0 + 128];
                float dd = sD[bank + i0] + sD[bank + i0 + 128];
                r += __fdividef(dd, ss);
            }
            #pragma unroll
            for (int o = 16; o; o >>= 1) r += __shfl_xor_sync(0xffffffffu, r, o);
            if (lane == 0)
                out[n * DH + h] = fmaxf(r + tbias[h], 0.0f);
        }
    }
}

// ---------------------------------------------------------------------------
extern "C" void kernel_launch(void* const* d_in, const int* in_sizes, int n_in,
                              void* d_out, int out_size) {
    const float* x    = (const float*)d_in[0];
    const float* mask = (const float*)d_in[1];
    const float* W1   = (const float*)d_in[2];
    const float* b1   = (const float*)d_in[3];
    const float* W2   = (const float*)d_in[4];
    const float* b2   = (const float*)d_in[5];
    const float* W3   = (const float*)d_in[6];
    // d_in[7] = b3: per-feature constant over l -> cancels in the softmax
    const float* tb   = (const float*)d_in[8];
    float* out = (float*)d_out;

    cudaFuncSetAttribute(k01,       cudaFuncAttributeMaxDynamicSharedMemorySize, K01_SMEM);
    cudaFuncSetAttribute(k2_filter, cudaFuncAttributeMaxDynamicSharedMemorySize, K2_SMEM);

    k01<<<640, 256, K01_SMEM>>>(W3, W1, W2, x, b1, b2);
    k2_filter<<<NCTA, 256, K2_SMEM>>>(x, mask, tb, out);
}